// round 9
// baseline (speedup 1.0000x reference)
#include <cuda_runtime.h>
#include <cuda_bf16.h>
#include <cstdint>

#define NBATCH 32
#define TLEN 256
#define VNODES 19
#define DM 256
#define DK 768
#define NT (NBATCH*TLEN)        // 8192
#define MROWS (NT*VNODES)       // 155648
#define MTILES (MROWS/128)      // 1216

typedef unsigned long long u64;

// scratch (device globals: allocation-free)
__device__ float g_y[(size_t)MROWS * DK];               // GEMM output, ~478MB
__device__ __nv_bfloat16 g_xhi[(size_t)MROWS * DM];     // X hi, swizzled tile layout
__device__ __nv_bfloat16 g_xlo[(size_t)MROWS * DM];     // X lo
__device__ __nv_bfloat16 g_bhi[DK*256];                 // W^T hi, swizzled n-major
__device__ __nv_bfloat16 g_blo[DK*256];                 // W^T lo
__device__ float g_An[3*8*VNODES*20];                   // normalized adjacency (padded)
__device__ float g_stats[2*DK];
__device__ float g_sb[2*DK];
__device__ float g_stats1[2*DM];
__device__ float g_sb1[2*DM];

__device__ __forceinline__ u64 pack2(float x, float y){
    u64 r; asm("mov.b64 %0, {%1,%2};" : "=l"(r) : "f"(x), "f"(y)); return r;
}
__device__ __forceinline__ void unpack2(u64 v, float &x, float &y){
    asm("mov.b64 {%0,%1}, %2;" : "=f"(x), "=f"(y) : "l"(v));
}
__device__ __forceinline__ void ffma2(u64 &d, u64 a, u64 b){
    asm("fma.rn.f32x2 %0, %1, %2, %0;" : "+l"(d) : "l"(a), "l"(b));
}
__device__ __forceinline__ uint32_t smem_u32(const void* p){
    uint32_t a;
    asm("{ .reg .u64 t; cvta.to.shared.u64 t, %1; cvt.u32.u64 %0, t; }" : "=r"(a) : "l"(p));
    return a;
}
__device__ __forceinline__ void cpa16(uint32_t d, const void* s){
    asm volatile("cp.async.cg.shared.global [%0], [%1], 16;" :: "r"(d), "l"(s));
}
#define CPA_COMMIT() asm volatile("cp.async.commit_group;" ::: "memory")
#define CPA_WAIT0()  asm volatile("cp.async.wait_group 0;" ::: "memory")

#define LDSM4(r0,r1,r2,r3,addr) \
    asm volatile("ldmatrix.sync.aligned.m8n8.x4.shared.b16 {%0,%1,%2,%3}, [%4];" \
                 : "=r"(r0),"=r"(r1),"=r"(r2),"=r"(r3) : "r"(addr))

#define MMA16816(c,a,b0,b1) \
    asm volatile("mma.sync.aligned.m16n8k16.row.col.f32.bf16.bf16.f32 " \
                 "{%0,%1,%2,%3},{%4,%5,%6,%7},{%8,%9},{%0,%1,%2,%3};" \
                 : "+f"((c)[0]),"+f"((c)[1]),"+f"((c)[2]),"+f"((c)[3]) \
                 : "r"((a)[0]),"r"((a)[1]),"r"((a)[2]),"r"((a)[3]),"r"(b0),"r"(b1))

// ---------------------------------------------------------------------------
__global__ void k_prep(const float* __restrict__ para) {
    int tid = threadIdx.x;
    for (int i = tid; i < 2*DK; i += blockDim.x) g_stats[i] = 0.f;
    for (int i = tid; i < 2*DM; i += blockDim.x) g_stats1[i] = 0.f;
    if (tid < 3*8*VNODES) {
        const float* src = para + tid*VNODES;
        float ss = 0.f;
        #pragma unroll
        for (int w = 0; w < VNODES; w++) ss += src[w]*src[w];
        float inv = 1.0f / (sqrtf(ss) + 1e-4f);
        float* dst = g_An + tid*20;
        #pragma unroll
        for (int w = 0; w < VNODES; w++) dst[w] = src[w]*inv;
        dst[VNODES] = 0.f;
    }
}

// ---------------------------------------------------------------------------
// Split X into bf16 hi/lo, pre-swizzled tile layout:
// byte(r,k) = r*512 + (((k>>3) ^ (r&7))<<4) + (k&7)*2   (r = row mod 128)
// ---------------------------------------------------------------------------
__global__ void k_split_x(const float* __restrict__ X) {
    size_t idx = (size_t)blockIdx.x * blockDim.x + threadIdx.x;
    if (idx >= (size_t)MROWS * 32) return;
    size_t m = idx >> 5;
    uint32_t c = (uint32_t)(idx & 31);
    const float4* s = (const float4*)(X + m*256 + c*8);
    float4 v0 = s[0], v1 = s[1];
    float f[8] = {v0.x, v0.y, v0.z, v0.w, v1.x, v1.y, v1.z, v1.w};
    uint32_t hi[4], lo[4];
    #pragma unroll
    for (int j = 0; j < 4; j++) {
        float a = f[2*j], b = f[2*j+1];
        __nv_bfloat16 ha = __float2bfloat16_rn(a);
        __nv_bfloat16 hb = __float2bfloat16_rn(b);
        __nv_bfloat16 la = __float2bfloat16_rn(a - __bfloat162float(ha));
        __nv_bfloat16 lb = __float2bfloat16_rn(b - __bfloat162float(hb));
        hi[j] = (uint32_t)__bfloat16_as_ushort(ha) | ((uint32_t)__bfloat16_as_ushort(hb) << 16);
        lo[j] = (uint32_t)__bfloat16_as_ushort(la) | ((uint32_t)__bfloat16_as_ushort(lb) << 16);
    }
    size_t dst = m*512 + (size_t)((c ^ (uint32_t)(m & 7)) << 4);
    *(uint4*)((char*)g_xhi + dst) = make_uint4(hi[0], hi[1], hi[2], hi[3]);
    *(uint4*)((char*)g_xlo + dst) = make_uint4(lo[0], lo[1], lo[2], lo[3]);
}

// ---------------------------------------------------------------------------
// Split W into bf16 hi/lo, transposed n-major [col][k], pre-swizzled.
// ---------------------------------------------------------------------------
__global__ void k_split_w(const float* __restrict__ W) {
    int idx = blockIdx.x * blockDim.x + threadIdx.x;    // 768*32 = 24576
    if (idx >= DK*32) return;
    int c   = idx & 31;
    int col = idx >> 5;
    int k0 = c*8;
    uint32_t hi[4], lo[4];
    #pragma unroll
    for (int j = 0; j < 4; j++) {
        float a = W[(size_t)(k0 + 2*j    )*DK + col];
        float b = W[(size_t)(k0 + 2*j + 1)*DK + col];
        __nv_bfloat16 ha = __float2bfloat16_rn(a);
        __nv_bfloat16 hb = __float2bfloat16_rn(b);
        __nv_bfloat16 la = __float2bfloat16_rn(a - __bfloat162float(ha));
        __nv_bfloat16 lb = __float2bfloat16_rn(b - __bfloat162float(hb));
        hi[j] = (uint32_t)__bfloat16_as_ushort(ha) | ((uint32_t)__bfloat16_as_ushort(hb) << 16);
        lo[j] = (uint32_t)__bfloat16_as_ushort(la) | ((uint32_t)__bfloat16_as_ushort(lb) << 16);
    }
    size_t dst = (size_t)col*512 + (size_t)((c ^ (col & 7)) << 4);
    *(uint4*)((char*)g_bhi + dst) = make_uint4(hi[0], hi[1], hi[2], hi[3]);
    *(uint4*)((char*)g_blo + dst) = make_uint4(lo[0], lo[1], lo[2], lo[3]);
}

// ---------------------------------------------------------------------------
// Pipelined tensor-core GEMM: y = X @ W, bf16 3-term split fused in one k-loop.
// 1216 CTAs x 128 rows; 256 threads = 4x2 warps, warp tile 32x32.
// 12 N-tiles of 64; B double-buffered at HALF-K granularity (24 chunks of
// 64 cols x 128 k, hi+lo = 32KB each). Accumulators persist across the two
// halves of an N-tile; epilogue after half 1 overlaps next chunk's cp.async.
// smem: Ahi 64KB | Alo 64KB | Bchunk[2] x 32KB = 192KB
// ---------------------------------------------------------------------------
#define OFF_ALO 65536u
#define OFF_B   131072u
#define B_CHUNK 32768u              // one chunk buffer: hi 16KB + lo 16KB
#define SMEM_GEMM (131072 + 2*32768)   // 196608 B

__global__ void __launch_bounds__(256) k_gemm_mma() {
    extern __shared__ char sm[];
    const int tid = threadIdx.x, lane = tid & 31, wid = tid >> 5;
    const int wm = wid & 3, wn = wid >> 2;     // 4 row-warps x 2 col-warps
    const size_t bm = blockIdx.x;

    const uint32_t sA = smem_u32(sm);

    // prologue: cp.async A (hi+lo) and B chunk 0 (nt=0, half=0)
    {
        const char* gh = (const char*)g_xhi + bm*65536;
        const char* gl = (const char*)g_xlo + bm*65536;
        #pragma unroll
        for (int u = 0; u < 16; u++) {
            int i = tid + u*256;
            cpa16(sA + (uint32_t)i*16u, gh + (size_t)i*16);
            cpa16(sA + OFF_ALO + (uint32_t)i*16u, gl + (size_t)i*16);
        }
        #pragma unroll
        for (int u = 0; u < 4; u++) {
            int i = tid + u*256;                 // i in 0..1023
            uint32_t dsto = (uint32_t)i*16u;
            size_t srco = (size_t)(i >> 4)*512 + (size_t)(i & 15)*16;
            cpa16(sA + OFF_B + dsto, (const char*)g_bhi + srco);
            cpa16(sA + OFF_B + 16384u + dsto, (const char*)g_blo + srco);
        }
        CPA_COMMIT();
    }
    CPA_WAIT0();
    __syncthreads();

    const int rA    = wm*32 + (lane & 15);
    const int koffA = lane >> 4;
    const int rB    = wn*32 + (lane & 7) + ((lane >> 4) << 3);
    const int koffB = (lane >> 3) & 1;
    const int r0    = wm*32 + (lane >> 2);
    const uint32_t axor = (uint32_t)(rA & 7), bxor = (uint32_t)(rB & 7);
    const uint32_t aHiB = sA + (uint32_t)rA * 512;
    const uint32_t aLoB = aHiB + OFF_ALO;

    float accH[2][4][4], accX[2][4][4];

    for (int ch = 0; ch < 24; ch++) {
        const int nt = ch >> 1, half = ch & 1;
        const int buf = ch & 1;

        // prefetch next chunk into the other buffer
        if (ch + 1 < 24) {
            const int nnt = (ch + 1) >> 1, nhalf = (ch + 1) & 1;
            uint32_t dst = sA + OFF_B + (uint32_t)(buf ^ 1) * B_CHUNK;
            const char* sh = (const char*)g_bhi + (size_t)nnt*32768 + (size_t)nhalf*256;
            const char* sl = (const char*)g_blo + (size_t)nnt*32768 + (size_t)nhalf*256;
            #pragma unroll
            for (int u = 0; u < 4; u++) {
                int i = tid + u*256;
                uint32_t dsto = (uint32_t)i*16u;
                size_t srco = (size_t)(i >> 4)*512 + (size_t)(i & 15)*16;
                cpa16(dst + dsto, sh + srco);
                cpa16(dst + 16384u + dsto, sl + srco);
            }
            CPA_COMMIT();
        }

        if (half == 0) {
            #pragma unroll
            for (int mi = 0; mi < 2; mi++)
                #pragma unroll
                for (int ni = 0; ni < 4; ni++)
                    #pragma unroll
                    for (int j = 0; j < 4; j++) { accH[mi][ni][j] = 0.f; accX[mi][ni][j] = 0.f; }
        }

        const uint32_t bHiB = sA + OFF_B + (uint32_t)buf * B_CHUNK + (uint32_t)rB * 256;
        const uint32_t bLoB = bHiB + 16384u;

        #pragma unroll
        for (int kcl = 0; kcl < 8; kcl++) {
            const int kcg = half*8 + kcl;
            uint32_t ach = (((uint32_t)(kcg*2 + koffA)) ^ axor) << 4;
            uint32_t bch = (((uint32_t)(kcl*2 + koffB)) ^ bxor) << 4;
            uint32_t ah0[4], ah1[4], al0[4], al1[4];
            uint32_t bh0[4], bh1[4], bl0[4], bl1[4];
            LDSM4(ah0[0], ah0[1], ah0[2], ah0[3], aHiB + ach);
            LDSM4(ah1[0], ah1[1], ah1[2], ah1[3], aHiB + 8192 + ach);
            LDSM4(al0[0], al0[1], al0[2], al0[3], aLoB + ach);
            LDSM4(al1[0], al1[1], al1[2], al1[3], aLoB + 8192 + ach);
            LDSM4(bh0[0], bh0[1], bh0[2], bh0[3], bHiB + bch);
            LDSM4(bh1[0], bh1[1], bh1[2], bh1[3], bHiB + 4096 + bch);
            LDSM4(bl0[0], bl0[1], bl0[2], bl0[3], bLoB + bch);
            LDSM4(bl1[0], bl1[1], bl1[2], bl1[3], bLoB + 4096 + bch);
            // hi*hi
            MMA16816(accH[0][0], ah0, bh0[0], bh0[1]);
            MMA16816(accH[0][1], ah0, bh0[2], bh0[3]);
            MMA16816(accH[0][2], ah0, bh1[0], bh1[1]);
            MMA16816(accH[0][3], ah0, bh1[2], bh1[3]);
            MMA16816(accH[1][0], ah1, bh0[0], bh0[1]);
            MMA16816(accH[1][1], ah1, bh0[2], bh0[3]);
            MMA16816(accH[1][2], ah1, bh1[0], bh1[1]);
            MMA16816(accH[1][3], ah1, bh1[2], bh1[3]);
            // lo*hi
            MMA16816(accX[0][0], al0, bh0[0], bh0[1]);
            MMA16816(accX[0][1], al0, bh0[2], bh0[3]);
            MMA16816(accX[0][2], al0, bh1[0], bh1[1]);
            MMA16816(accX[0][3], al0, bh1[2], bh1[3]);
            MMA16816(accX[1][0], al1, bh0[0], bh0[1]);
            MMA16816(accX[1][1], al1, bh0[2], bh0[3]);
            MMA16816(accX[1][2], al1, bh1[0], bh1[1]);
            MMA16816(accX[1][3], al1, bh1[2], bh1[3]);
            // hi*lo
            MMA16816(accX[0][0], ah0, bl0[0], bl0[1]);
            MMA16816(accX[0][1], ah0, bl0[2], bl0[3]);
            MMA16816(accX[0][2], ah0, bl1[0], bl1[1]);
            MMA16816(accX[0][3], ah0, bl1[2], bl1[3]);
            MMA16816(accX[1][0], ah1, bl0[0], bl0[1]);
            MMA16816(accX[1][1], ah1, bl0[2], bl0[3]);
            MMA16816(accX[1][2], ah1, bl1[0], bl1[1]);
            MMA16816(accX[1][3], ah1, bl1[2], bl1[3]);
        }

        if (half == 1) {
            // merge split terms and run epilogue for this N-tile
            #pragma unroll
            for (int mi = 0; mi < 2; mi++)
                #pragma unroll
                for (int ni = 0; ni < 4; ni++)
                    #pragma unroll
                    for (int j = 0; j < 4; j++)
                        accH[mi][ni][j] += accX[mi][ni][j];

            #pragma unroll
            for (int mi = 0; mi < 2; mi++) {
                #pragma unroll
                for (int ni = 0; ni < 4; ni++) {
                    int cb = wn*32 + ((ni >> 1) << 4) + ((ni & 1) << 3) + ((lane & 3) << 1);
                    float* p = g_y + (bm*128 + r0 + mi*16)*DK + nt*64 + cb;
                    *(float2*)p = make_float2(accH[mi][ni][0], accH[mi][ni][1]);
                    *(float2*)(p + (size_t)8*DK) = make_float2(accH[mi][ni][2], accH[mi][ni][3]);
                }
            }
            #pragma unroll
            for (int ni = 0; ni < 4; ni++) {
                float s0 = accH[0][ni][0] + accH[0][ni][2] + accH[1][ni][0] + accH[1][ni][2];
                float s1 = accH[0][ni][1] + accH[0][ni][3] + accH[1][ni][1] + accH[1][ni][3];
                float q0 = accH[0][ni][0]*accH[0][ni][0] + accH[0][ni][2]*accH[0][ni][2]
                         + accH[1][ni][0]*accH[1][ni][0] + accH[1][ni][2]*accH[1][ni][2];
                float q1 = accH[0][ni][1]*accH[0][ni][1] + accH[0][ni][3]*accH[0][ni][3]
                         + accH[1][ni][1]*accH[1][ni][1] + accH[1][ni][3]*accH[1][ni][3];
                #pragma unroll
                for (int off = 4; off < 32; off <<= 1) {
                    s0 += __shfl_xor_sync(0xFFFFFFFFu, s0, off);
                    s1 += __shfl_xor_sync(0xFFFFFFFFu, s1, off);
                    q0 += __shfl_xor_sync(0xFFFFFFFFu, q0, off);
                    q1 += __shfl_xor_sync(0xFFFFFFFFu, q1, off);
                }
                if (lane < 4) {
                    int col = nt*64 + wn*32 + ((ni >> 1) << 4) + ((ni & 1) << 3) + lane*2;
                    atomicAdd(&g_stats[col],         s0);
                    atomicAdd(&g_stats[col + 1],     s1);
                    atomicAdd(&g_stats[DK + col],    q0);
                    atomicAdd(&g_stats[DK + col+1],  q1);
                }
            }
        }

        if (ch + 1 < 24) CPA_WAIT0();
        __syncthreads();
    }
}

// ---------------------------------------------------------------------------
__global__ void k_fin_bn(const float* __restrict__ gamma, const float* __restrict__ beta) {
    int d = threadIdx.x;
    float inv = 1.0f / (float)MROWS;
    float mean = g_stats[d] * inv;
    float var  = g_stats[DK + d] * inv - mean*mean;
    float sc = gamma[d] * rsqrtf(var + 1e-5f);
    g_sb[d]      = sc;
    g_sb[DK + d] = beta[d] - mean*sc;
}

// ---------------------------------------------------------------------------
// Per-(n,t): z[c,w] = sum_{k,v} yhat[v, k*256+c] * An[k, c%8, v, w] + x[n,t,w,c]
// smem-staged y tile (bulk float4-coalesced), BN affine applied on load.
// ---------------------------------------------------------------------------
__global__ void __launch_bounds__(256, 2) k_contract(const float* __restrict__ X,
                                                     float* __restrict__ out) {
    extern __shared__ float smf[];
    float* ysh = smf;                    // 19*768
    float* Ash = smf + VNODES*DK;        // 3*8*19*20
    int tid = threadIdx.x;
    size_t nt = blockIdx.x;

    const float4* yb = (const float4*)(g_y + nt * (size_t)(VNODES*DK));
    float4* ysh4 = (float4*)ysh;
    for (int i = tid; i < VNODES*DK/4; i += 256) {
        int d = (i*4) % DK;
        float4 v = yb[i];
        float4 sc = *(const float4*)&g_sb[d];
        float4 of = *(const float4*)&g_sb[DK + d];
        v.x = fmaf(v.x, sc.x, of.x); v.y = fmaf(v.y, sc.y, of.y);
        v.z = fmaf(v.z, sc.z, of.z); v.w = fmaf(v.w, sc.w, of.w);
        ysh4[i] = v;
    }
    for (int i = tid; i < 3*8*VNODES*20; i += 256) Ash[i] = g_An[i];
    __syncthreads();

    int c = tid;
    int g = c & 7;
    float yv[3][VNODES];
    #pragma unroll
    for (int k = 0; k < 3; k++)
        #pragma unroll
        for (int v = 0; v < VNODES; v++)
            yv[k][v] = ysh[v*DK + k*DM + c];

    u64 acc[10];
    #pragma unroll
    for (int p = 0; p < 10; p++) acc[p] = 0ull;
    #pragma unroll
    for (int k = 0; k < 3; k++) {
        const u64* Ab = (const u64*)(Ash + (size_t)((k*8 + g)*VNODES)*20);
        #pragma unroll
        for (int v = 0; v < VNODES; v++) {
            u64 yp = pack2(yv[k][v], yv[k][v]);
            const u64* ar = Ab + v*10;
            #pragma unroll
            for (int p = 0; p < 10; p++) ffma2(acc[p], yp, ar[p]);
        }
    }

    float z[20];
    #pragma unroll
    for (int p = 0; p < 10; p++) unpack2(acc[p], z[2*p], z[2*p+1]);

    const float* xb = X + nt * (size_t)(VNODES*DM) + c;
    float* ob = out + nt * (size_t)(VNODES*DM) + c;
    float s = 0.f, q = 0.f;
    #pragma unroll
    for (int w = 0; w < VNODES; w++) {
        float zv = z[w] + xb[(size_t)w * DM];
        s += zv; q += zv*zv;
        ob[(size_t)w * DM] = zv;
    }
    atomicAdd(&g_stats1[c], s);
    atomicAdd(&g_stats1[DM + c], q);
}

__global__ void k_fin_bn1(const float* __restrict__ gamma, const float* __restrict__ beta) {
    int d = threadIdx.x;
    float inv = 1.0f / (float)MROWS;
    float mean = g_stats1[d] * inv;
    float var  = g_stats1[DM + d] * inv - mean*mean;
    float sc = gamma[d] * rsqrtf(var + 1e-5f);
    g_sb1[d]      = sc;
    g_sb1[DM + d] = beta[d] - mean*sc;
}

// ---------------------------------------------------------------------------
__global__ void k_relu(float* __restrict__ out) {
    size_t total4 = (size_t)MROWS * DM / 4;
    float4* o4 = (float4*)out;
    for (size_t i = (size_t)blockIdx.x * blockDim.x + threadIdx.x; i < total4;
         i += (size_t)gridDim.x * blockDim.x) {
        int c = (int)(i & 63) * 4;
        float4 v = o4[i];
        float4 sc = *(const float4*)&g_sb1[c];
        float4 of = *(const float4*)&g_sb1[DM + c];
        v.x = fmaxf(fmaf(v.x, sc.x, of.x), 0.f);
        v.y = fmaxf(fmaf(v.y, sc.y, of.y), 0.f);
        v.z = fmaxf(fmaf(v.z, sc.z, of.z), 0.f);
        v.w = fmaxf(fmaf(v.w, sc.w, of.w), 0.f);
        o4[i] = v;
    }
}

extern "C" void kernel_launch(void* const* d_in, const int* in_sizes, int n_in,
                              void* d_out, int out_size) {
    const float* x    = (const float*)d_in[0];
    const float* para = (const float*)d_in[1];
    const float* W    = (const float*)d_in[2];
    // d_in[3] linear_bias: cancels under training-mode BN (mean subtraction)
    const float* bng  = (const float*)d_in[4];
    const float* bnb  = (const float*)d_in[5];
    const float* bn1g = (const float*)d_in[6];
    const float* bn1b = (const float*)d_in[7];
    float* out = (float*)d_out;

    const int smem_contract = (VNODES*DK + 3*8*VNODES*20) * 4;   // 94848 B
    cudaFuncSetAttribute(k_contract, cudaFuncAttributeMaxDynamicSharedMemorySize,
                         smem_contract);
    cudaFuncSetAttribute(k_gemm_mma, cudaFuncAttributeMaxDynamicSharedMemorySize,
                         SMEM_GEMM);

    k_prep<<<1, 512>>>(para);
    k_split_x<<<(MROWS*32)/256, 256>>>(x);
    k_split_w<<<96, 256>>>(W);
    k_gemm_mma<<<MTILES, 256, SMEM_GEMM>>>();
    k_fin_bn<<<1, DK>>>(bng, bnb);
    k_contract<<<NT, 256, smem_contract>>>(x, out);
    k_fin_bn1<<<1, DM>>>(bn1g, bn1b);
    k_relu<<<2048, 256>>>(out);
}

// round 10
// speedup vs baseline: 1.2097x; 1.2097x over previous
#include <cuda_runtime.h>
#include <cuda_bf16.h>
#include <cstdint>

#define NBATCH 32
#define TLEN 256
#define VNODES 19
#define DM 256
#define DK 768
#define NT (NBATCH*TLEN)        // 8192
#define MROWS (NT*VNODES)       // 155648
#define MTILES (MROWS/128)      // 1216

typedef unsigned long long u64;

// scratch (device globals: allocation-free)
__device__ float g_y[(size_t)MROWS * DK];               // GEMM output, ~478MB
__device__ __nv_bfloat16 g_bhi[DK*256];                 // W^T hi, swizzled n-major
__device__ __nv_bfloat16 g_blo[DK*256];                 // W^T lo
__device__ float g_An[3*8*VNODES*20];                   // normalized adjacency (padded)
__device__ float g_stats[2*DK];
__device__ float g_sb[2*DK];
__device__ float g_stats1[2*DM];
__device__ float g_sb1[2*DM];

__device__ __forceinline__ u64 pack2(float x, float y){
    u64 r; asm("mov.b64 %0, {%1,%2};" : "=l"(r) : "f"(x), "f"(y)); return r;
}
__device__ __forceinline__ void unpack2(u64 v, float &x, float &y){
    asm("mov.b64 {%0,%1}, %2;" : "=f"(x), "=f"(y) : "l"(v));
}
__device__ __forceinline__ void ffma2(u64 &d, u64 a, u64 b){
    asm("fma.rn.f32x2 %0, %1, %2, %0;" : "+l"(d) : "l"(a), "l"(b));
}
__device__ __forceinline__ uint32_t smem_u32(const void* p){
    uint32_t a;
    asm("{ .reg .u64 t; cvta.to.shared.u64 t, %1; cvt.u32.u64 %0, t; }" : "=r"(a) : "l"(p));
    return a;
}
__device__ __forceinline__ void cpa16(uint32_t d, const void* s){
    asm volatile("cp.async.cg.shared.global [%0], [%1], 16;" :: "r"(d), "l"(s));
}
#define CPA_COMMIT() asm volatile("cp.async.commit_group;" ::: "memory")
#define CPA_WAIT0()  asm volatile("cp.async.wait_group 0;" ::: "memory")
#define CPA_WAIT1()  asm volatile("cp.async.wait_group 1;" ::: "memory")

#define LDSM4(r0,r1,r2,r3,addr) \
    asm volatile("ldmatrix.sync.aligned.m8n8.x4.shared.b16 {%0,%1,%2,%3}, [%4];" \
                 : "=r"(r0),"=r"(r1),"=r"(r2),"=r"(r3) : "r"(addr))

#define MMA16816(c,a,b0,b1) \
    asm volatile("mma.sync.aligned.m16n8k16.row.col.f32.bf16.bf16.f32 " \
                 "{%0,%1,%2,%3},{%4,%5,%6,%7},{%8,%9},{%0,%1,%2,%3};" \
                 : "+f"((c)[0]),"+f"((c)[1]),"+f"((c)[2]),"+f"((c)[3]) \
                 : "r"((a)[0]),"r"((a)[1]),"r"((a)[2]),"r"((a)[3]),"r"(b0),"r"(b1))

// ---------------------------------------------------------------------------
__global__ void k_prep(const float* __restrict__ para) {
    int tid = threadIdx.x;
    for (int i = tid; i < 2*DK; i += blockDim.x) g_stats[i] = 0.f;
    for (int i = tid; i < 2*DM; i += blockDim.x) g_stats1[i] = 0.f;
    if (tid < 3*8*VNODES) {
        const float* src = para + tid*VNODES;
        float ss = 0.f;
        #pragma unroll
        for (int w = 0; w < VNODES; w++) ss += src[w]*src[w];
        float inv = 1.0f / (sqrtf(ss) + 1e-4f);
        float* dst = g_An + tid*20;
        #pragma unroll
        for (int w = 0; w < VNODES; w++) dst[w] = src[w]*inv;
        dst[VNODES] = 0.f;
    }
}

// ---------------------------------------------------------------------------
// Split W into bf16 hi/lo, transposed n-major [col][k], pre-swizzled.
// ---------------------------------------------------------------------------
__global__ void k_split_w(const float* __restrict__ W) {
    int idx = blockIdx.x * blockDim.x + threadIdx.x;    // 768*32 = 24576
    if (idx >= DK*32) return;
    int c   = idx & 31;
    int col = idx >> 5;
    int k0 = c*8;
    uint32_t hi[4], lo[4];
    #pragma unroll
    for (int j = 0; j < 4; j++) {
        float a = W[(size_t)(k0 + 2*j    )*DK + col];
        float b = W[(size_t)(k0 + 2*j + 1)*DK + col];
        __nv_bfloat16 ha = __float2bfloat16_rn(a);
        __nv_bfloat16 hb = __float2bfloat16_rn(b);
        __nv_bfloat16 la = __float2bfloat16_rn(a - __bfloat162float(ha));
        __nv_bfloat16 lb = __float2bfloat16_rn(b - __bfloat162float(hb));
        hi[j] = (uint32_t)__bfloat16_as_ushort(ha) | ((uint32_t)__bfloat16_as_ushort(hb) << 16);
        lo[j] = (uint32_t)__bfloat16_as_ushort(la) | ((uint32_t)__bfloat16_as_ushort(lb) << 16);
    }
    size_t dst = (size_t)col*512 + (size_t)((c ^ (col & 7)) << 4);
    *(uint4*)((char*)g_bhi + dst) = make_uint4(hi[0], hi[1], hi[2], hi[3]);
    *(uint4*)((char*)g_blo + dst) = make_uint4(lo[0], lo[1], lo[2], lo[3]);
}

// ---------------------------------------------------------------------------
// Pipelined tensor-core GEMM: y = X @ W, bf16 3-term split fused in one k-loop.
// A (X tile) is converted fp32->bf16 hi/lo + swizzled INLINE in the prologue
// (no separate split_x kernel, no xhi/xlo round-trip).
// 1216 CTAs x 128 rows; 384 threads = 4x3 warps, warp tile 32x16.
// 16 N-tiles of 48, cp.async double-buffered B.
// smem: Ahi 64KB | Alo 64KB | B[2] x (hi 24KB + lo 24KB) = 224KB
// ---------------------------------------------------------------------------
#define GEMM_THREADS 384
#define B_TILE_HALF 24576u          // 48 cols * 512 B
#define B_BUF_BYTES 49152u          // hi + lo
#define OFF_ALO 65536u
#define OFF_B   131072u
#define SMEM_GEMM (131072 + 2*49152)   // 229376 B

__global__ void __launch_bounds__(GEMM_THREADS) k_gemm_mma(const float* __restrict__ X) {
    extern __shared__ char sm[];
    const int tid = threadIdx.x, lane = tid & 31, wid = tid >> 5;   // wid 0..11
    const int wm = wid & 3, wn = wid >> 2;     // 4 row-warps x 3 col-warps
    const size_t bm = blockIdx.x;

    const uint32_t sA = smem_u32(sm);

    // prologue: B tile 0 via cp.async (in flight), A converted inline
    for (int i = tid; i < 1536; i += GEMM_THREADS) {
        cpa16(sA + OFF_B + (uint32_t)i*16u, (const char*)g_bhi + (size_t)i*16);
        cpa16(sA + OFF_B + B_TILE_HALF + (uint32_t)i*16u, (const char*)g_blo + (size_t)i*16);
    }
    CPA_COMMIT();
    {
        const float4* Xb = (const float4*)(X + bm*32768);
        for (int i = tid; i < 8192; i += GEMM_THREADS) {
            int rr = i >> 6, c4 = i & 63;
            float4 v = Xb[i];
            float f[4] = {v.x, v.y, v.z, v.w};
            union { __nv_bfloat16 b[4]; u64 u; } hp, lp;
            #pragma unroll
            for (int j = 0; j < 4; j++) {
                __nv_bfloat16 h = __float2bfloat16_rn(f[j]);
                hp.b[j] = h;
                lp.b[j] = __float2bfloat16_rn(f[j] - __bfloat162float(h));
            }
            uint32_t base = (uint32_t)rr*512u
                          + ((((uint32_t)(c4 >> 1)) ^ (uint32_t)(rr & 7)) << 4)
                          + (uint32_t)((c4 & 1) * 8);
            *(u64*)(sm + base) = hp.u;
            *(u64*)(sm + OFF_ALO + base) = lp.u;
        }
    }
    CPA_WAIT0();
    __syncthreads();

    const int rA    = wm*32 + (lane & 15);
    const int koffA = lane >> 4;
    const int rB    = wn*16 + (lane & 7) + ((lane >> 4) << 3);
    const int koffB = (lane >> 3) & 1;
    const int r0    = wm*32 + (lane >> 2);
    const uint32_t axor = (uint32_t)(rA & 7), bxor = (uint32_t)(rB & 7);
    const uint32_t aHiB = sA + (uint32_t)rA * 512;
    const uint32_t aLoB = aHiB + OFF_ALO;

    for (int nt = 0; nt < 16; nt++) {
        const int buf = nt & 1;
        // prefetch next B tile into the other buffer (overlaps k-loop+epilogue)
        if (nt + 1 < 16) {
            uint32_t dst = sA + OFF_B + (uint32_t)(buf ^ 1) * B_BUF_BYTES;
            size_t src = (size_t)(nt + 1) * B_TILE_HALF;
            for (int i = tid; i < 1536; i += GEMM_THREADS) {
                cpa16(dst + (uint32_t)i*16u, (const char*)g_bhi + src + (size_t)i*16);
                cpa16(dst + B_TILE_HALF + (uint32_t)i*16u, (const char*)g_blo + src + (size_t)i*16);
            }
            CPA_COMMIT();
        }

        float accH[2][2][4], accX[2][2][4];
        #pragma unroll
        for (int mi = 0; mi < 2; mi++)
            #pragma unroll
            for (int ni = 0; ni < 2; ni++)
                #pragma unroll
                for (int j = 0; j < 4; j++) { accH[mi][ni][j] = 0.f; accX[mi][ni][j] = 0.f; }

        const uint32_t bHiB = sA + OFF_B + (uint32_t)buf * B_BUF_BYTES + (uint32_t)rB * 512;
        const uint32_t bLoB = bHiB + B_TILE_HALF;

        #pragma unroll
        for (int kc = 0; kc < 16; kc++) {
            uint32_t ach = (((uint32_t)(kc*2 + koffA)) ^ axor) << 4;
            uint32_t bch = (((uint32_t)(kc*2 + koffB)) ^ bxor) << 4;
            uint32_t ah0[4], ah1[4], al0[4], al1[4], bh[4], bl[4];
            LDSM4(ah0[0], ah0[1], ah0[2], ah0[3], aHiB + ach);
            LDSM4(ah1[0], ah1[1], ah1[2], ah1[3], aHiB + 8192 + ach);
            LDSM4(al0[0], al0[1], al0[2], al0[3], aLoB + ach);
            LDSM4(al1[0], al1[1], al1[2], al1[3], aLoB + 8192 + ach);
            LDSM4(bh[0], bh[1], bh[2], bh[3], bHiB + bch);
            LDSM4(bl[0], bl[1], bl[2], bl[3], bLoB + bch);
            // hi*hi
            MMA16816(accH[0][0], ah0, bh[0], bh[1]);
            MMA16816(accH[0][1], ah0, bh[2], bh[3]);
            MMA16816(accH[1][0], ah1, bh[0], bh[1]);
            MMA16816(accH[1][1], ah1, bh[2], bh[3]);
            // lo*hi
            MMA16816(accX[0][0], al0, bh[0], bh[1]);
            MMA16816(accX[0][1], al0, bh[2], bh[3]);
            MMA16816(accX[1][0], al1, bh[0], bh[1]);
            MMA16816(accX[1][1], al1, bh[2], bh[3]);
            // hi*lo
            MMA16816(accX[0][0], ah0, bl[0], bl[1]);
            MMA16816(accX[0][1], ah0, bl[2], bl[3]);
            MMA16816(accX[1][0], ah1, bl[0], bl[1]);
            MMA16816(accX[1][1], ah1, bl[2], bl[3]);
        }

        float acc[2][2][4];
        #pragma unroll
        for (int mi = 0; mi < 2; mi++)
            #pragma unroll
            for (int ni = 0; ni < 2; ni++)
                #pragma unroll
                for (int j = 0; j < 4; j++)
                    acc[mi][ni][j] = accH[mi][ni][j] + accX[mi][ni][j];

        // epilogue: write g_y + BN stats (overlaps in-flight prefetch)
        #pragma unroll
        for (int mi = 0; mi < 2; mi++) {
            #pragma unroll
            for (int ni = 0; ni < 2; ni++) {
                int cb = wn*16 + ni*8 + ((lane & 3) << 1);
                float* p = g_y + (bm*128 + r0 + mi*16)*DK + nt*48 + cb;
                *(float2*)p = make_float2(acc[mi][ni][0], acc[mi][ni][1]);
                *(float2*)(p + (size_t)8*DK) = make_float2(acc[mi][ni][2], acc[mi][ni][3]);
            }
        }
        #pragma unroll
        for (int ni = 0; ni < 2; ni++) {
            float s0 = acc[0][ni][0] + acc[0][ni][2] + acc[1][ni][0] + acc[1][ni][2];
            float s1 = acc[0][ni][1] + acc[0][ni][3] + acc[1][ni][1] + acc[1][ni][3];
            float q0 = acc[0][ni][0]*acc[0][ni][0] + acc[0][ni][2]*acc[0][ni][2]
                     + acc[1][ni][0]*acc[1][ni][0] + acc[1][ni][2]*acc[1][ni][2];
            float q1 = acc[0][ni][1]*acc[0][ni][1] + acc[0][ni][3]*acc[0][ni][3]
                     + acc[1][ni][1]*acc[1][ni][1] + acc[1][ni][3]*acc[1][ni][3];
            #pragma unroll
            for (int off = 4; off < 32; off <<= 1) {
                s0 += __shfl_xor_sync(0xFFFFFFFFu, s0, off);
                s1 += __shfl_xor_sync(0xFFFFFFFFu, s1, off);
                q0 += __shfl_xor_sync(0xFFFFFFFFu, q0, off);
                q1 += __shfl_xor_sync(0xFFFFFFFFu, q1, off);
            }
            if (lane < 4) {
                int col = nt*48 + wn*16 + ni*8 + lane*2;
                atomicAdd(&g_stats[col],         s0);
                atomicAdd(&g_stats[col + 1],     s1);
                atomicAdd(&g_stats[DK + col],    q0);
                atomicAdd(&g_stats[DK + col+1],  q1);
            }
        }

        if (nt + 1 < 16) CPA_WAIT0();
        __syncthreads();
    }
}

// ---------------------------------------------------------------------------
__global__ void k_fin_bn(const float* __restrict__ gamma, const float* __restrict__ beta) {
    int d = threadIdx.x;
    float inv = 1.0f / (float)MROWS;
    float mean = g_stats[d] * inv;
    float var  = g_stats[DK + d] * inv - mean*mean;
    float sc = gamma[d] * rsqrtf(var + 1e-5f);
    g_sb[d]      = sc;
    g_sb[DK + d] = beta[d] - mean*sc;
}

// ---------------------------------------------------------------------------
// Per-(n,t): z[c,w] = sum_{k,v} yhat[v, k*256+c] * An[k, c%8, v, w] + x[n,t,w,c]
// 4 tiles per block, cp.async DOUBLE-BUFFERED y tiles: loads overlap compute.
// BN affine applied at smem-read; BN1 stats accumulated across all 4 tiles.
// smem: ybuf[2] x 58368B + A 36480B = 153216 B
// ---------------------------------------------------------------------------
#define YTILE_F (VNODES*DK)          // 14592 floats
#define YTILE_B (YTILE_F*4)          // 58368 bytes
#define SMEM_CONTRACT (2*YTILE_B + 3*8*VNODES*20*4)   // 153216 B

__global__ void __launch_bounds__(256) k_contract(const float* __restrict__ X,
                                                  float* __restrict__ out) {
    extern __shared__ float smf[];
    float* Ash = smf + 2*YTILE_F;
    const int tid = threadIdx.x;
    const size_t nt0 = (size_t)blockIdx.x * 4;
    const uint32_t sb = smem_u32(smf);

    // prologue: A table + first y tile
    for (int i = tid; i < 3*8*VNODES*20; i += 256) Ash[i] = g_An[i];
    {
        const char* src = (const char*)(g_y + nt0 * YTILE_F);
        for (int i = tid; i < YTILE_B/16; i += 256)
            cpa16(sb + (uint32_t)i*16u, src + (size_t)i*16);
        CPA_COMMIT();
    }

    const int c = tid, g = c & 7;
    float sc[3], of[3];
    #pragma unroll
    for (int k = 0; k < 3; k++) {
        sc[k] = g_sb[k*DM + c];
        of[k] = g_sb[DK + k*DM + c];
    }

    float s_tot = 0.f, q_tot = 0.f;

    for (int r = 0; r < 4; r++) {
        const size_t nt = nt0 + r;
        // prefetch next tile into the other buffer
        if (r < 3) {
            const char* src = (const char*)(g_y + (nt + 1) * YTILE_F);
            uint32_t dst = sb + (((r + 1) & 1) ? (uint32_t)YTILE_B : 0u);
            for (int i = tid; i < YTILE_B/16; i += 256)
                cpa16(dst + (uint32_t)i*16u, src + (size_t)i*16);
            CPA_COMMIT();
            CPA_WAIT1();
        } else {
            CPA_WAIT0();
        }
        __syncthreads();

        const float* ysh = smf + ((r & 1) ? YTILE_F : 0);

        u64 acc[10];
        #pragma unroll
        for (int p = 0; p < 10; p++) acc[p] = 0ull;
        #pragma unroll
        for (int k = 0; k < 3; k++) {
            const u64* Ab = (const u64*)(Ash + (size_t)((k*8 + g)*VNODES)*20);
            #pragma unroll
            for (int v = 0; v < VNODES; v++) {
                float yv = fmaf(ysh[v*DK + k*DM + c], sc[k], of[k]);
                u64 yp = pack2(yv, yv);
                const u64* ar = Ab + v*10;
                #pragma unroll
                for (int p = 0; p < 10; p++) ffma2(acc[p], yp, ar[p]);
            }
        }

        float z[20];
        #pragma unroll
        for (int p = 0; p < 10; p++) unpack2(acc[p], z[2*p], z[2*p+1]);

        const float* xb = X + nt * (size_t)(VNODES*DM) + c;
        float* ob = out + nt * (size_t)(VNODES*DM) + c;
        #pragma unroll
        for (int w = 0; w < VNODES; w++) {
            float zv = z[w] + xb[(size_t)w * DM];
            s_tot += zv; q_tot += zv*zv;
            ob[(size_t)w * DM] = zv;
        }
        __syncthreads();   // all threads done with this buffer before next reuse
    }
    atomicAdd(&g_stats1[c], s_tot);
    atomicAdd(&g_stats1[DM + c], q_tot);
}

__global__ void k_fin_bn1(const float* __restrict__ gamma, const float* __restrict__ beta) {
    int d = threadIdx.x;
    float inv = 1.0f / (float)MROWS;
    float mean = g_stats1[d] * inv;
    float var  = g_stats1[DM + d] * inv - mean*mean;
    float sc = gamma[d] * rsqrtf(var + 1e-5f);
    g_sb1[d]      = sc;
    g_sb1[DM + d] = beta[d] - mean*sc;
}

// ---------------------------------------------------------------------------
__global__ void k_relu(float* __restrict__ out) {
    size_t total4 = (size_t)MROWS * DM / 4;
    float4* o4 = (float4*)out;
    for (size_t i = (size_t)blockIdx.x * blockDim.x + threadIdx.x; i < total4;
         i += (size_t)gridDim.x * blockDim.x) {
        int c = (int)(i & 63) * 4;
        float4 v = o4[i];
        float4 sc = *(const float4*)&g_sb1[c];
        float4 of = *(const float4*)&g_sb1[DM + c];
        v.x = fmaxf(fmaf(v.x, sc.x, of.x), 0.f);
        v.y = fmaxf(fmaf(v.y, sc.y, of.y), 0.f);
        v.z = fmaxf(fmaf(v.z, sc.z, of.z), 0.f);
        v.w = fmaxf(fmaf(v.w, sc.w, of.w), 0.f);
        o4[i] = v;
    }
}

extern "C" void kernel_launch(void* const* d_in, const int* in_sizes, int n_in,
                              void* d_out, int out_size) {
    const float* x    = (const float*)d_in[0];
    const float* para = (const float*)d_in[1];
    const float* W    = (const float*)d_in[2];
    // d_in[3] linear_bias: cancels under training-mode BN (mean subtraction)
    const float* bng  = (const float*)d_in[4];
    const float* bnb  = (const float*)d_in[5];
    const float* bn1g = (const float*)d_in[6];
    const float* bn1b = (const float*)d_in[7];
    float* out = (float*)d_out;

    cudaFuncSetAttribute(k_contract, cudaFuncAttributeMaxDynamicSharedMemorySize,
                         SMEM_CONTRACT);
    cudaFuncSetAttribute(k_gemm_mma, cudaFuncAttributeMaxDynamicSharedMemorySize,
                         SMEM_GEMM);

    k_prep<<<1, 512>>>(para);
    k_split_w<<<96, 256>>>(W);
    k_gemm_mma<<<MTILES, GEMM_THREADS, SMEM_GEMM>>>(x);
    k_fin_bn<<<1, DK>>>(bng, bnb);
    k_contract<<<NT/4, 256, SMEM_CONTRACT>>>(x, out);
    k_fin_bn1<<<1, DM>>>(bn1g, bn1b);
    k_relu<<<2048, 256>>>(out);
}

// round 11
// speedup vs baseline: 1.2322x; 1.0186x over previous
#include <cuda_runtime.h>
#include <cuda_bf16.h>
#include <cstdint>

#define NBATCH 32
#define TLEN 256
#define VNODES 19
#define DM 256
#define DK 768
#define NT (NBATCH*TLEN)        // 8192
#define MROWS (NT*VNODES)       // 155648
#define MTILES (MROWS/128)      // 1216

typedef unsigned long long u64;

// scratch (device globals: allocation-free)
__device__ float g_y[(size_t)MROWS * DK];               // GEMM output, ~478MB
__device__ __nv_bfloat16 g_bhi[DK*256];                 // W^T hi, swizzled n-major
__device__ __nv_bfloat16 g_blo[DK*256];                 // W^T lo
__device__ float g_An[3*8*VNODES*20];                   // normalized adjacency (padded)
__device__ float g_stats[2*DK];
__device__ float g_sb[2*DK];
__device__ float g_stats1[2*DM];
__device__ float g_sb1[2*DM];

__device__ __forceinline__ u64 pack2(float x, float y){
    u64 r; asm("mov.b64 %0, {%1,%2};" : "=l"(r) : "f"(x), "f"(y)); return r;
}
__device__ __forceinline__ void unpack2(u64 v, float &x, float &y){
    asm("mov.b64 {%0,%1}, %2;" : "=f"(x), "=f"(y) : "l"(v));
}
__device__ __forceinline__ void ffma2(u64 &d, u64 a, u64 b){
    asm("fma.rn.f32x2 %0, %1, %2, %0;" : "+l"(d) : "l"(a), "l"(b));
}
__device__ __forceinline__ uint32_t smem_u32(const void* p){
    uint32_t a;
    asm("{ .reg .u64 t; cvta.to.shared.u64 t, %1; cvt.u32.u64 %0, t; }" : "=r"(a) : "l"(p));
    return a;
}
__device__ __forceinline__ void cpa16(uint32_t d, const void* s){
    asm volatile("cp.async.cg.shared.global [%0], [%1], 16;" :: "r"(d), "l"(s));
}
#define CPA_COMMIT() asm volatile("cp.async.commit_group;" ::: "memory")
#define CPA_WAIT0()  asm volatile("cp.async.wait_group 0;" ::: "memory")
#define CPA_WAIT1()  asm volatile("cp.async.wait_group 1;" ::: "memory")

#define LDSM4(r0,r1,r2,r3,addr) \
    asm volatile("ldmatrix.sync.aligned.m8n8.x4.shared.b16 {%0,%1,%2,%3}, [%4];" \
                 : "=r"(r0),"=r"(r1),"=r"(r2),"=r"(r3) : "r"(addr))

#define MMA16816(c,a,b0,b1) \
    asm volatile("mma.sync.aligned.m16n8k16.row.col.f32.bf16.bf16.f32 " \
                 "{%0,%1,%2,%3},{%4,%5,%6,%7},{%8,%9},{%0,%1,%2,%3};" \
                 : "+f"((c)[0]),"+f"((c)[1]),"+f"((c)[2]),"+f"((c)[3]) \
                 : "r"((a)[0]),"r"((a)[1]),"r"((a)[2]),"r"((a)[3]),"r"(b0),"r"(b1))

// ---------------------------------------------------------------------------
__global__ void k_prep(const float* __restrict__ para) {
    int tid = threadIdx.x;
    for (int i = tid; i < 2*DK; i += blockDim.x) g_stats[i] = 0.f;
    for (int i = tid; i < 2*DM; i += blockDim.x) g_stats1[i] = 0.f;
    if (tid < 3*8*VNODES) {
        const float* src = para + tid*VNODES;
        float ss = 0.f;
        #pragma unroll
        for (int w = 0; w < VNODES; w++) ss += src[w]*src[w];
        float inv = 1.0f / (sqrtf(ss) + 1e-4f);
        float* dst = g_An + tid*20;
        #pragma unroll
        for (int w = 0; w < VNODES; w++) dst[w] = src[w]*inv;
        dst[VNODES] = 0.f;
    }
}

// ---------------------------------------------------------------------------
// Split W into bf16 hi/lo, transposed n-major [col][k], pre-swizzled.
// ---------------------------------------------------------------------------
__global__ void k_split_w(const float* __restrict__ W) {
    int idx = blockIdx.x * blockDim.x + threadIdx.x;    // 768*32 = 24576
    if (idx >= DK*32) return;
    int c   = idx & 31;
    int col = idx >> 5;
    int k0 = c*8;
    uint32_t hi[4], lo[4];
    #pragma unroll
    for (int j = 0; j < 4; j++) {
        float a = W[(size_t)(k0 + 2*j    )*DK + col];
        float b = W[(size_t)(k0 + 2*j + 1)*DK + col];
        __nv_bfloat16 ha = __float2bfloat16_rn(a);
        __nv_bfloat16 hb = __float2bfloat16_rn(b);
        __nv_bfloat16 la = __float2bfloat16_rn(a - __bfloat162float(ha));
        __nv_bfloat16 lb = __float2bfloat16_rn(b - __bfloat162float(hb));
        hi[j] = (uint32_t)__bfloat16_as_ushort(ha) | ((uint32_t)__bfloat16_as_ushort(hb) << 16);
        lo[j] = (uint32_t)__bfloat16_as_ushort(la) | ((uint32_t)__bfloat16_as_ushort(lb) << 16);
    }
    size_t dst = (size_t)col*512 + (size_t)((c ^ (col & 7)) << 4);
    *(uint4*)((char*)g_bhi + dst) = make_uint4(hi[0], hi[1], hi[2], hi[3]);
    *(uint4*)((char*)g_blo + dst) = make_uint4(lo[0], lo[1], lo[2], lo[3]);
}

// ---------------------------------------------------------------------------
// Pipelined tensor-core GEMM: y = X @ W, bf16 3-term split fused in one k-loop.
// A converted fp32->bf16 hi/lo + swizzled inline in the prologue.
// 1216 CTAs x 128 rows; 512 threads = 4x4 warps, warp tile 32x16.
// 12 N-tiles of 64; B double-buffered at HALF-K chunks (24 chunks of
// 64 cols x 128 k, hi+lo = 32KB). Acc persists across the 2 halves; epilogue
// after half 1 overlaps the next chunk's cp.async.
// smem: Ahi 64KB | Alo 64KB | Bchunk[2] x 32KB = 192KB
// ---------------------------------------------------------------------------
#define GEMM_THREADS 512
#define B_CHUNK 32768u              // hi 16KB + lo 16KB
#define OFF_ALO 65536u
#define OFF_B   131072u
#define SMEM_GEMM (131072 + 2*32768)   // 196608 B

__global__ void __launch_bounds__(GEMM_THREADS) k_gemm_mma(const float* __restrict__ X) {
    extern __shared__ char sm[];
    const int tid = threadIdx.x, lane = tid & 31, wid = tid >> 5;   // 0..15
    const int wm = wid & 3, wn = wid >> 2;     // 4 row-warps x 4 col-warps
    const size_t bm = blockIdx.x;

    const uint32_t sA = smem_u32(sm);

    // prologue: B chunk 0 via cp.async (in flight), A converted inline
    #pragma unroll
    for (int u = 0; u < 2; u++) {
        int i = tid + u*512;                    // 0..1023: 64 cols x 16 units
        uint32_t dsto = (uint32_t)i*16u;
        size_t srco = (size_t)(i >> 4)*512 + (size_t)(i & 15)*16;
        cpa16(sA + OFF_B + dsto, (const char*)g_bhi + srco);
        cpa16(sA + OFF_B + 16384u + dsto, (const char*)g_blo + srco);
    }
    CPA_COMMIT();
    {
        const float4* Xb = (const float4*)(X + bm*32768);
        #pragma unroll
        for (int u = 0; u < 16; u++) {
            int i = tid + u*512;
            int rr = i >> 6, c4 = i & 63;
            float4 v = Xb[i];
            float f[4] = {v.x, v.y, v.z, v.w};
            union { __nv_bfloat16 b[4]; u64 u2; } hp, lp;
            #pragma unroll
            for (int j = 0; j < 4; j++) {
                __nv_bfloat16 h = __float2bfloat16_rn(f[j]);
                hp.b[j] = h;
                lp.b[j] = __float2bfloat16_rn(f[j] - __bfloat162float(h));
            }
            uint32_t base = (uint32_t)rr*512u
                          + ((((uint32_t)(c4 >> 1)) ^ (uint32_t)(rr & 7)) << 4)
                          + (uint32_t)((c4 & 1) * 8);
            *(u64*)(sm + base) = hp.u2;
            *(u64*)(sm + OFF_ALO + base) = lp.u2;
        }
    }
    CPA_WAIT0();
    __syncthreads();

    const int rA    = wm*32 + (lane & 15);
    const int koffA = lane >> 4;
    const int rB    = wn*16 + (lane & 7) + ((lane >> 4) << 3);
    const int koffB = (lane >> 3) & 1;
    const int r0    = wm*32 + (lane >> 2);
    const uint32_t axor = (uint32_t)(rA & 7), bxor = (uint32_t)(rB & 7);
    const uint32_t aHiB = sA + (uint32_t)rA * 512;
    const uint32_t aLoB = aHiB + OFF_ALO;

    float accH[2][2][4], accX[2][2][4];

    for (int ch = 0; ch < 24; ch++) {
        const int nt = ch >> 1, half = ch & 1;
        const int buf = ch & 1;

        // prefetch next chunk into the other buffer
        if (ch + 1 < 24) {
            const int nnt = (ch + 1) >> 1, nhalf = (ch + 1) & 1;
            uint32_t dst = sA + OFF_B + (uint32_t)(buf ^ 1) * B_CHUNK;
            const char* sh = (const char*)g_bhi + (size_t)nnt*32768 + (size_t)nhalf*256;
            const char* sl = (const char*)g_blo + (size_t)nnt*32768 + (size_t)nhalf*256;
            #pragma unroll
            for (int u = 0; u < 2; u++) {
                int i = tid + u*512;
                uint32_t dsto = (uint32_t)i*16u;
                size_t srco = (size_t)(i >> 4)*512 + (size_t)(i & 15)*16;
                cpa16(dst + dsto, sh + srco);
                cpa16(dst + 16384u + dsto, sl + srco);
            }
            CPA_COMMIT();
        }

        if (half == 0) {
            #pragma unroll
            for (int mi = 0; mi < 2; mi++)
                #pragma unroll
                for (int ni = 0; ni < 2; ni++)
                    #pragma unroll
                    for (int j = 0; j < 4; j++) { accH[mi][ni][j] = 0.f; accX[mi][ni][j] = 0.f; }
        }

        const uint32_t bHiB = sA + OFF_B + (uint32_t)buf * B_CHUNK + (uint32_t)rB * 256;
        const uint32_t bLoB = bHiB + 16384u;

        #pragma unroll
        for (int kcl = 0; kcl < 8; kcl++) {
            const int kcg = half*8 + kcl;
            uint32_t ach = (((uint32_t)(kcg*2 + koffA)) ^ axor) << 4;
            uint32_t bch = (((uint32_t)(kcl*2 + koffB)) ^ bxor) << 4;
            uint32_t ah0[4], ah1[4], al0[4], al1[4], bh[4], bl[4];
            LDSM4(ah0[0], ah0[1], ah0[2], ah0[3], aHiB + ach);
            LDSM4(ah1[0], ah1[1], ah1[2], ah1[3], aHiB + 8192 + ach);
            LDSM4(al0[0], al0[1], al0[2], al0[3], aLoB + ach);
            LDSM4(al1[0], al1[1], al1[2], al1[3], aLoB + 8192 + ach);
            LDSM4(bh[0], bh[1], bh[2], bh[3], bHiB + bch);
            LDSM4(bl[0], bl[1], bl[2], bl[3], bLoB + bch);
            // hi*hi
            MMA16816(accH[0][0], ah0, bh[0], bh[1]);
            MMA16816(accH[0][1], ah0, bh[2], bh[3]);
            MMA16816(accH[1][0], ah1, bh[0], bh[1]);
            MMA16816(accH[1][1], ah1, bh[2], bh[3]);
            // lo*hi
            MMA16816(accX[0][0], al0, bh[0], bh[1]);
            MMA16816(accX[0][1], al0, bh[2], bh[3]);
            MMA16816(accX[1][0], al1, bh[0], bh[1]);
            MMA16816(accX[1][1], al1, bh[2], bh[3]);
            // hi*lo
            MMA16816(accX[0][0], ah0, bl[0], bl[1]);
            MMA16816(accX[0][1], ah0, bl[2], bl[3]);
            MMA16816(accX[1][0], ah1, bl[0], bl[1]);
            MMA16816(accX[1][1], ah1, bl[2], bl[3]);
        }

        if (half == 1) {
            float acc[2][2][4];
            #pragma unroll
            for (int mi = 0; mi < 2; mi++)
                #pragma unroll
                for (int ni = 0; ni < 2; ni++)
                    #pragma unroll
                    for (int j = 0; j < 4; j++)
                        acc[mi][ni][j] = accH[mi][ni][j] + accX[mi][ni][j];

            // epilogue: write g_y + BN stats (overlaps in-flight prefetch)
            #pragma unroll
            for (int mi = 0; mi < 2; mi++) {
                #pragma unroll
                for (int ni = 0; ni < 2; ni++) {
                    int cb = wn*16 + ni*8 + ((lane & 3) << 1);
                    float* p = g_y + (bm*128 + r0 + mi*16)*DK + nt*64 + cb;
                    *(float2*)p = make_float2(acc[mi][ni][0], acc[mi][ni][1]);
                    *(float2*)(p + (size_t)8*DK) = make_float2(acc[mi][ni][2], acc[mi][ni][3]);
                }
            }
            #pragma unroll
            for (int ni = 0; ni < 2; ni++) {
                float s0 = acc[0][ni][0] + acc[0][ni][2] + acc[1][ni][0] + acc[1][ni][2];
                float s1 = acc[0][ni][1] + acc[0][ni][3] + acc[1][ni][1] + acc[1][ni][3];
                float q0 = acc[0][ni][0]*acc[0][ni][0] + acc[0][ni][2]*acc[0][ni][2]
                         + acc[1][ni][0]*acc[1][ni][0] + acc[1][ni][2]*acc[1][ni][2];
                float q1 = acc[0][ni][1]*acc[0][ni][1] + acc[0][ni][3]*acc[0][ni][3]
                         + acc[1][ni][1]*acc[1][ni][1] + acc[1][ni][3]*acc[1][ni][3];
                #pragma unroll
                for (int off = 4; off < 32; off <<= 1) {
                    s0 += __shfl_xor_sync(0xFFFFFFFFu, s0, off);
                    s1 += __shfl_xor_sync(0xFFFFFFFFu, s1, off);
                    q0 += __shfl_xor_sync(0xFFFFFFFFu, q0, off);
                    q1 += __shfl_xor_sync(0xFFFFFFFFu, q1, off);
                }
                if (lane < 4) {
                    int col = nt*64 + wn*16 + ni*8 + lane*2;
                    atomicAdd(&g_stats[col],         s0);
                    atomicAdd(&g_stats[col + 1],     s1);
                    atomicAdd(&g_stats[DK + col],    q0);
                    atomicAdd(&g_stats[DK + col+1],  q1);
                }
            }
        }

        if (ch + 1 < 24) CPA_WAIT0();
        __syncthreads();
    }
}

// ---------------------------------------------------------------------------
__global__ void k_fin_bn(const float* __restrict__ gamma, const float* __restrict__ beta) {
    int d = threadIdx.x;
    float inv = 1.0f / (float)MROWS;
    float mean = g_stats[d] * inv;
    float var  = g_stats[DK + d] * inv - mean*mean;
    float sc = gamma[d] * rsqrtf(var + 1e-5f);
    g_sb[d]      = sc;
    g_sb[DK + d] = beta[d] - mean*sc;
}

// ---------------------------------------------------------------------------
// Per-(n,t): z[c,w] = sum_{k,v} yhat[v, k*256+c] * An[k, c%8, v, w] + x[n,t,w,c]
// 4 tiles per block, cp.async DOUBLE-BUFFERED y tiles.
// smem: ybuf[2] x 58368B + A 36480B = 153216 B
// ---------------------------------------------------------------------------
#define YTILE_F (VNODES*DK)          // 14592 floats
#define YTILE_B (YTILE_F*4)          // 58368 bytes
#define SMEM_CONTRACT (2*YTILE_B + 3*8*VNODES*20*4)   // 153216 B

__global__ void __launch_bounds__(256) k_contract(const float* __restrict__ X,
                                                  float* __restrict__ out) {
    extern __shared__ float smf[];
    float* Ash = smf + 2*YTILE_F;
    const int tid = threadIdx.x;
    const size_t nt0 = (size_t)blockIdx.x * 4;
    const uint32_t sb = smem_u32(smf);

    for (int i = tid; i < 3*8*VNODES*20; i += 256) Ash[i] = g_An[i];
    {
        const char* src = (const char*)(g_y + nt0 * YTILE_F);
        for (int i = tid; i < YTILE_B/16; i += 256)
            cpa16(sb + (uint32_t)i*16u, src + (size_t)i*16);
        CPA_COMMIT();
    }

    const int c = tid, g = c & 7;
    float sc[3], of[3];
    #pragma unroll
    for (int k = 0; k < 3; k++) {
        sc[k] = g_sb[k*DM + c];
        of[k] = g_sb[DK + k*DM + c];
    }

    float s_tot = 0.f, q_tot = 0.f;

    for (int r = 0; r < 4; r++) {
        const size_t nt = nt0 + r;
        if (r < 3) {
            const char* src = (const char*)(g_y + (nt + 1) * YTILE_F);
            uint32_t dst = sb + (((r + 1) & 1) ? (uint32_t)YTILE_B : 0u);
            for (int i = tid; i < YTILE_B/16; i += 256)
                cpa16(dst + (uint32_t)i*16u, src + (size_t)i*16);
            CPA_COMMIT();
            CPA_WAIT1();
        } else {
            CPA_WAIT0();
        }
        __syncthreads();

        const float* ysh = smf + ((r & 1) ? YTILE_F : 0);

        u64 acc[10];
        #pragma unroll
        for (int p = 0; p < 10; p++) acc[p] = 0ull;
        #pragma unroll
        for (int k = 0; k < 3; k++) {
            const u64* Ab = (const u64*)(Ash + (size_t)((k*8 + g)*VNODES)*20);
            #pragma unroll
            for (int v = 0; v < VNODES; v++) {
                float yv = fmaf(ysh[v*DK + k*DM + c], sc[k], of[k]);
                u64 yp = pack2(yv, yv);
                const u64* ar = Ab + v*10;
                #pragma unroll
                for (int p = 0; p < 10; p++) ffma2(acc[p], yp, ar[p]);
            }
        }

        float z[20];
        #pragma unroll
        for (int p = 0; p < 10; p++) unpack2(acc[p], z[2*p], z[2*p+1]);

        const float* xb = X + nt * (size_t)(VNODES*DM) + c;
        float* ob = out + nt * (size_t)(VNODES*DM) + c;
        #pragma unroll
        for (int w = 0; w < VNODES; w++) {
            float zv = z[w] + xb[(size_t)w * DM];
            s_tot += zv; q_tot += zv*zv;
            ob[(size_t)w * DM] = zv;
        }
        __syncthreads();
    }
    atomicAdd(&g_stats1[c], s_tot);
    atomicAdd(&g_stats1[DM + c], q_tot);
}

__global__ void k_fin_bn1(const float* __restrict__ gamma, const float* __restrict__ beta) {
    int d = threadIdx.x;
    float inv = 1.0f / (float)MROWS;
    float mean = g_stats1[d] * inv;
    float var  = g_stats1[DM + d] * inv - mean*mean;
    float sc = gamma[d] * rsqrtf(var + 1e-5f);
    g_sb1[d]      = sc;
    g_sb1[DM + d] = beta[d] - mean*sc;
}

// ---------------------------------------------------------------------------
__global__ void k_relu(float* __restrict__ out) {
    size_t total4 = (size_t)MROWS * DM / 4;
    float4* o4 = (float4*)out;
    for (size_t i = (size_t)blockIdx.x * blockDim.x + threadIdx.x; i < total4;
         i += (size_t)gridDim.x * blockDim.x) {
        int c = (int)(i & 63) * 4;
        float4 v = o4[i];
        float4 sc = *(const float4*)&g_sb1[c];
        float4 of = *(const float4*)&g_sb1[DM + c];
        v.x = fmaxf(fmaf(v.x, sc.x, of.x), 0.f);
        v.y = fmaxf(fmaf(v.y, sc.y, of.y), 0.f);
        v.z = fmaxf(fmaf(v.z, sc.z, of.z), 0.f);
        v.w = fmaxf(fmaf(v.w, sc.w, of.w), 0.f);
        o4[i] = v;
    }
}

extern "C" void kernel_launch(void* const* d_in, const int* in_sizes, int n_in,
                              void* d_out, int out_size) {
    const float* x    = (const float*)d_in[0];
    const float* para = (const float*)d_in[1];
    const float* W    = (const float*)d_in[2];
    // d_in[3] linear_bias: cancels under training-mode BN (mean subtraction)
    const float* bng  = (const float*)d_in[4];
    const float* bnb  = (const float*)d_in[5];
    const float* bn1g = (const float*)d_in[6];
    const float* bn1b = (const float*)d_in[7];
    float* out = (float*)d_out;

    cudaFuncSetAttribute(k_contract, cudaFuncAttributeMaxDynamicSharedMemorySize,
                         SMEM_CONTRACT);
    cudaFuncSetAttribute(k_gemm_mma, cudaFuncAttributeMaxDynamicSharedMemorySize,
                         SMEM_GEMM);

    k_prep<<<1, 512>>>(para);
    k_split_w<<<96, 256>>>(W);
    k_gemm_mma<<<MTILES, GEMM_THREADS, SMEM_GEMM>>>(x);
    k_fin_bn<<<1, DK>>>(bng, bnb);
    k_contract<<<NT/4, 256, SMEM_CONTRACT>>>(x, out);
    k_fin_bn1<<<1, DM>>>(bn1g, bn1b);
    k_relu<<<2048, 256>>>(out);
}

// round 12
// speedup vs baseline: 1.3003x; 1.0553x over previous
#include <cuda_runtime.h>
#include <cuda_bf16.h>
#include <cuda_fp16.h>
#include <cstdint>

#define NBATCH 32
#define TLEN 256
#define VNODES 19
#define DM 256
#define DK 768
#define NT (NBATCH*TLEN)        // 8192
#define MROWS (NT*VNODES)       // 155648
#define MTILES (MROWS/128)      // 1216

typedef unsigned long long u64;

// scratch (device globals: allocation-free)
__device__ __half g_y[(size_t)MROWS * DK];              // GEMM output, fp16, ~239MB
__device__ __nv_bfloat16 g_bhi[DK*256];                 // W^T hi, swizzled n-major
__device__ __nv_bfloat16 g_blo[DK*256];                 // W^T lo
__device__ float g_An[3*8*VNODES*20];                   // normalized adjacency (padded)
__device__ float g_stats[2*DK];
__device__ float g_sb[2*DK];
__device__ float g_stats1[2*DM];
__device__ float g_sb1[2*DM];

__device__ __forceinline__ u64 pack2(float x, float y){
    u64 r; asm("mov.b64 %0, {%1,%2};" : "=l"(r) : "f"(x), "f"(y)); return r;
}
__device__ __forceinline__ void unpack2(u64 v, float &x, float &y){
    asm("mov.b64 {%0,%1}, %2;" : "=f"(x), "=f"(y) : "l"(v));
}
__device__ __forceinline__ void ffma2(u64 &d, u64 a, u64 b){
    asm("fma.rn.f32x2 %0, %1, %2, %0;" : "+l"(d) : "l"(a), "l"(b));
}
__device__ __forceinline__ uint32_t smem_u32(const void* p){
    uint32_t a;
    asm("{ .reg .u64 t; cvta.to.shared.u64 t, %1; cvt.u32.u64 %0, t; }" : "=r"(a) : "l"(p));
    return a;
}
__device__ __forceinline__ void cpa16(uint32_t d, const void* s){
    asm volatile("cp.async.cg.shared.global [%0], [%1], 16;" :: "r"(d), "l"(s));
}
#define CPA_COMMIT() asm volatile("cp.async.commit_group;" ::: "memory")
#define CPA_WAIT0()  asm volatile("cp.async.wait_group 0;" ::: "memory")
#define CPA_WAIT1()  asm volatile("cp.async.wait_group 1;" ::: "memory")

#define LDSM4(r0,r1,r2,r3,addr) \
    asm volatile("ldmatrix.sync.aligned.m8n8.x4.shared.b16 {%0,%1,%2,%3}, [%4];" \
                 : "=r"(r0),"=r"(r1),"=r"(r2),"=r"(r3) : "r"(addr))

#define MMA16816(c,a,b0,b1) \
    asm volatile("mma.sync.aligned.m16n8k16.row.col.f32.bf16.bf16.f32 " \
                 "{%0,%1,%2,%3},{%4,%5,%6,%7},{%8,%9},{%0,%1,%2,%3};" \
                 : "+f"((c)[0]),"+f"((c)[1]),"+f"((c)[2]),"+f"((c)[3]) \
                 : "r"((a)[0]),"r"((a)[1]),"r"((a)[2]),"r"((a)[3]),"r"(b0),"r"(b1))

// ---------------------------------------------------------------------------
__global__ void k_prep(const float* __restrict__ para) {
    int tid = threadIdx.x;
    for (int i = tid; i < 2*DK; i += blockDim.x) g_stats[i] = 0.f;
    for (int i = tid; i < 2*DM; i += blockDim.x) g_stats1[i] = 0.f;
    if (tid < 3*8*VNODES) {
        const float* src = para + tid*VNODES;
        float ss = 0.f;
        #pragma unroll
        for (int w = 0; w < VNODES; w++) ss += src[w]*src[w];
        float inv = 1.0f / (sqrtf(ss) + 1e-4f);
        float* dst = g_An + tid*20;
        #pragma unroll
        for (int w = 0; w < VNODES; w++) dst[w] = src[w]*inv;
        dst[VNODES] = 0.f;
    }
}

// ---------------------------------------------------------------------------
// Split W into bf16 hi/lo, transposed n-major [col][k], pre-swizzled.
// ---------------------------------------------------------------------------
__global__ void k_split_w(const float* __restrict__ W) {
    int idx = blockIdx.x * blockDim.x + threadIdx.x;    // 768*32 = 24576
    if (idx >= DK*32) return;
    int c   = idx & 31;
    int col = idx >> 5;
    int k0 = c*8;
    uint32_t hi[4], lo[4];
    #pragma unroll
    for (int j = 0; j < 4; j++) {
        float a = W[(size_t)(k0 + 2*j    )*DK + col];
        float b = W[(size_t)(k0 + 2*j + 1)*DK + col];
        __nv_bfloat16 ha = __float2bfloat16_rn(a);
        __nv_bfloat16 hb = __float2bfloat16_rn(b);
        __nv_bfloat16 la = __float2bfloat16_rn(a - __bfloat162float(ha));
        __nv_bfloat16 lb = __float2bfloat16_rn(b - __bfloat162float(hb));
        hi[j] = (uint32_t)__bfloat16_as_ushort(ha) | ((uint32_t)__bfloat16_as_ushort(hb) << 16);
        lo[j] = (uint32_t)__bfloat16_as_ushort(la) | ((uint32_t)__bfloat16_as_ushort(lb) << 16);
    }
    size_t dst = (size_t)col*512 + (size_t)((c ^ (col & 7)) << 4);
    *(uint4*)((char*)g_bhi + dst) = make_uint4(hi[0], hi[1], hi[2], hi[3]);
    *(uint4*)((char*)g_blo + dst) = make_uint4(lo[0], lo[1], lo[2], lo[3]);
}

// ---------------------------------------------------------------------------
// Pipelined tensor-core GEMM: y = X @ W, bf16 3-term split fused in one k-loop.
// A converted fp32->bf16 hi/lo + swizzled inline in the prologue.
// 1216 CTAs x 128 rows; 512 threads = 4x4 warps, warp tile 32x16.
// 12 N-tiles of 64; B double-buffered at HALF-K chunks. y stored as fp16.
// smem: Ahi 64KB | Alo 64KB | Bchunk[2] x 32KB = 192KB
// ---------------------------------------------------------------------------
#define GEMM_THREADS 512
#define B_CHUNK 32768u              // hi 16KB + lo 16KB
#define OFF_ALO 65536u
#define OFF_B   131072u
#define SMEM_GEMM (131072 + 2*32768)   // 196608 B

__global__ void __launch_bounds__(GEMM_THREADS) k_gemm_mma(const float* __restrict__ X) {
    extern __shared__ char sm[];
    const int tid = threadIdx.x, lane = tid & 31, wid = tid >> 5;   // 0..15
    const int wm = wid & 3, wn = wid >> 2;     // 4 row-warps x 4 col-warps
    const size_t bm = blockIdx.x;

    const uint32_t sA = smem_u32(sm);

    // prologue: B chunk 0 via cp.async (in flight), A converted inline
    #pragma unroll
    for (int u = 0; u < 2; u++) {
        int i = tid + u*512;                    // 0..1023: 64 cols x 16 units
        uint32_t dsto = (uint32_t)i*16u;
        size_t srco = (size_t)(i >> 4)*512 + (size_t)(i & 15)*16;
        cpa16(sA + OFF_B + dsto, (const char*)g_bhi + srco);
        cpa16(sA + OFF_B + 16384u + dsto, (const char*)g_blo + srco);
    }
    CPA_COMMIT();
    {
        const float4* Xb = (const float4*)(X + bm*32768);
        #pragma unroll
        for (int u = 0; u < 16; u++) {
            int i = tid + u*512;
            int rr = i >> 6, c4 = i & 63;
            float4 v = Xb[i];
            float f[4] = {v.x, v.y, v.z, v.w};
            union { __nv_bfloat16 b[4]; u64 u2; } hp, lp;
            #pragma unroll
            for (int j = 0; j < 4; j++) {
                __nv_bfloat16 h = __float2bfloat16_rn(f[j]);
                hp.b[j] = h;
                lp.b[j] = __float2bfloat16_rn(f[j] - __bfloat162float(h));
            }
            uint32_t base = (uint32_t)rr*512u
                          + ((((uint32_t)(c4 >> 1)) ^ (uint32_t)(rr & 7)) << 4)
                          + (uint32_t)((c4 & 1) * 8);
            *(u64*)(sm + base) = hp.u2;
            *(u64*)(sm + OFF_ALO + base) = lp.u2;
        }
    }
    CPA_WAIT0();
    __syncthreads();

    const int rA    = wm*32 + (lane & 15);
    const int koffA = lane >> 4;
    const int rB    = wn*16 + (lane & 7) + ((lane >> 4) << 3);
    const int koffB = (lane >> 3) & 1;
    const int r0    = wm*32 + (lane >> 2);
    const uint32_t axor = (uint32_t)(rA & 7), bxor = (uint32_t)(rB & 7);
    const uint32_t aHiB = sA + (uint32_t)rA * 512;
    const uint32_t aLoB = aHiB + OFF_ALO;

    float accH[2][2][4], accX[2][2][4];

    for (int ch = 0; ch < 24; ch++) {
        const int nt = ch >> 1, half = ch & 1;
        const int buf = ch & 1;

        // prefetch next chunk into the other buffer
        if (ch + 1 < 24) {
            const int nnt = (ch + 1) >> 1, nhalf = (ch + 1) & 1;
            uint32_t dst = sA + OFF_B + (uint32_t)(buf ^ 1) * B_CHUNK;
            const char* sh = (const char*)g_bhi + (size_t)nnt*32768 + (size_t)nhalf*256;
            const char* sl = (const char*)g_blo + (size_t)nnt*32768 + (size_t)nhalf*256;
            #pragma unroll
            for (int u = 0; u < 2; u++) {
                int i = tid + u*512;
                uint32_t dsto = (uint32_t)i*16u;
                size_t srco = (size_t)(i >> 4)*512 + (size_t)(i & 15)*16;
                cpa16(dst + dsto, sh + srco);
                cpa16(dst + 16384u + dsto, sl + srco);
            }
            CPA_COMMIT();
        }

        if (half == 0) {
            #pragma unroll
            for (int mi = 0; mi < 2; mi++)
                #pragma unroll
                for (int ni = 0; ni < 2; ni++)
                    #pragma unroll
                    for (int j = 0; j < 4; j++) { accH[mi][ni][j] = 0.f; accX[mi][ni][j] = 0.f; }
        }

        const uint32_t bHiB = sA + OFF_B + (uint32_t)buf * B_CHUNK + (uint32_t)rB * 256;
        const uint32_t bLoB = bHiB + 16384u;

        #pragma unroll
        for (int kcl = 0; kcl < 8; kcl++) {
            const int kcg = half*8 + kcl;
            uint32_t ach = (((uint32_t)(kcg*2 + koffA)) ^ axor) << 4;
            uint32_t bch = (((uint32_t)(kcl*2 + koffB)) ^ bxor) << 4;
            uint32_t ah0[4], ah1[4], al0[4], al1[4], bh[4], bl[4];
            LDSM4(ah0[0], ah0[1], ah0[2], ah0[3], aHiB + ach);
            LDSM4(ah1[0], ah1[1], ah1[2], ah1[3], aHiB + 8192 + ach);
            LDSM4(al0[0], al0[1], al0[2], al0[3], aLoB + ach);
            LDSM4(al1[0], al1[1], al1[2], al1[3], aLoB + 8192 + ach);
            LDSM4(bh[0], bh[1], bh[2], bh[3], bHiB + bch);
            LDSM4(bl[0], bl[1], bl[2], bl[3], bLoB + bch);
            // hi*hi
            MMA16816(accH[0][0], ah0, bh[0], bh[1]);
            MMA16816(accH[0][1], ah0, bh[2], bh[3]);
            MMA16816(accH[1][0], ah1, bh[0], bh[1]);
            MMA16816(accH[1][1], ah1, bh[2], bh[3]);
            // lo*hi
            MMA16816(accX[0][0], al0, bh[0], bh[1]);
            MMA16816(accX[0][1], al0, bh[2], bh[3]);
            MMA16816(accX[1][0], al1, bh[0], bh[1]);
            MMA16816(accX[1][1], al1, bh[2], bh[3]);
            // hi*lo
            MMA16816(accX[0][0], ah0, bl[0], bl[1]);
            MMA16816(accX[0][1], ah0, bl[2], bl[3]);
            MMA16816(accX[1][0], ah1, bl[0], bl[1]);
            MMA16816(accX[1][1], ah1, bl[2], bl[3]);
        }

        if (half == 1) {
            float acc[2][2][4];
            #pragma unroll
            for (int mi = 0; mi < 2; mi++)
                #pragma unroll
                for (int ni = 0; ni < 2; ni++)
                    #pragma unroll
                    for (int j = 0; j < 4; j++)
                        acc[mi][ni][j] = accH[mi][ni][j] + accX[mi][ni][j];

            // epilogue: write g_y (fp16) + BN stats (fp32, exact)
            #pragma unroll
            for (int mi = 0; mi < 2; mi++) {
                #pragma unroll
                for (int ni = 0; ni < 2; ni++) {
                    int cb = wn*16 + ni*8 + ((lane & 3) << 1);
                    __half* p = g_y + (bm*128 + r0 + mi*16)*DK + nt*64 + cb;
                    *(__half2*)p = __floats2half2_rn(acc[mi][ni][0], acc[mi][ni][1]);
                    *(__half2*)(p + (size_t)8*DK) = __floats2half2_rn(acc[mi][ni][2], acc[mi][ni][3]);
                }
            }
            #pragma unroll
            for (int ni = 0; ni < 2; ni++) {
                float s0 = acc[0][ni][0] + acc[0][ni][2] + acc[1][ni][0] + acc[1][ni][2];
                float s1 = acc[0][ni][1] + acc[0][ni][3] + acc[1][ni][1] + acc[1][ni][3];
                float q0 = acc[0][ni][0]*acc[0][ni][0] + acc[0][ni][2]*acc[0][ni][2]
                         + acc[1][ni][0]*acc[1][ni][0] + acc[1][ni][2]*acc[1][ni][2];
                float q1 = acc[0][ni][1]*acc[0][ni][1] + acc[0][ni][3]*acc[0][ni][3]
                         + acc[1][ni][1]*acc[1][ni][1] + acc[1][ni][3]*acc[1][ni][3];
                #pragma unroll
                for (int off = 4; off < 32; off <<= 1) {
                    s0 += __shfl_xor_sync(0xFFFFFFFFu, s0, off);
                    s1 += __shfl_xor_sync(0xFFFFFFFFu, s1, off);
                    q0 += __shfl_xor_sync(0xFFFFFFFFu, q0, off);
                    q1 += __shfl_xor_sync(0xFFFFFFFFu, q1, off);
                }
                if (lane < 4) {
                    int col = nt*64 + wn*16 + ni*8 + lane*2;
                    atomicAdd(&g_stats[col],         s0);
                    atomicAdd(&g_stats[col + 1],     s1);
                    atomicAdd(&g_stats[DK + col],    q0);
                    atomicAdd(&g_stats[DK + col+1],  q1);
                }
            }
        }

        if (ch + 1 < 24) CPA_WAIT0();
        __syncthreads();
    }
}

// ---------------------------------------------------------------------------
__global__ void k_fin_bn(const float* __restrict__ gamma, const float* __restrict__ beta) {
    int d = threadIdx.x;
    float inv = 1.0f / (float)MROWS;
    float mean = g_stats[d] * inv;
    float var  = g_stats[DK + d] * inv - mean*mean;
    float sc = gamma[d] * rsqrtf(var + 1e-5f);
    g_sb[d]      = sc;
    g_sb[DK + d] = beta[d] - mean*sc;
}

// ---------------------------------------------------------------------------
// Per-(n,t): z[c,w] = sum_{k,v} yhat[v, k*256+c] * An[k, c%8, v, w] + x[n,t,w,c]
// 4 tiles per block, cp.async DOUBLE-BUFFERED fp16 y tiles.
// smem: ybuf[2] x 29184B + A 36480B = 94848 B -> 2 CTAs/SM
// ---------------------------------------------------------------------------
#define YTILE_E (VNODES*DK)          // 14592 elements
#define YTILE_B (YTILE_E*2)          // 29184 bytes (fp16)
#define SMEM_CONTRACT (2*YTILE_B + 3*8*VNODES*20*4)   // 94848 B

__global__ void __launch_bounds__(256, 2) k_contract(const float* __restrict__ X,
                                                     float* __restrict__ out) {
    extern __shared__ char smc[];
    float* Ash = (float*)(smc + 2*YTILE_B);
    const int tid = threadIdx.x;
    const size_t nt0 = (size_t)blockIdx.x * 4;
    const uint32_t sb = smem_u32(smc);

    for (int i = tid; i < 3*8*VNODES*20; i += 256) Ash[i] = g_An[i];
    {
        const char* src = (const char*)(g_y + nt0 * YTILE_E);
        for (int i = tid; i < YTILE_B/16; i += 256)
            cpa16(sb + (uint32_t)i*16u, src + (size_t)i*16);
        CPA_COMMIT();
    }

    const int c = tid, g = c & 7;
    float sc[3], of[3];
    #pragma unroll
    for (int k = 0; k < 3; k++) {
        sc[k] = g_sb[k*DM + c];
        of[k] = g_sb[DK + k*DM + c];
    }

    float s_tot = 0.f, q_tot = 0.f;

    for (int r = 0; r < 4; r++) {
        const size_t nt = nt0 + r;
        if (r < 3) {
            const char* src = (const char*)(g_y + (nt + 1) * YTILE_E);
            uint32_t dst = sb + (((r + 1) & 1) ? (uint32_t)YTILE_B : 0u);
            for (int i = tid; i < YTILE_B/16; i += 256)
                cpa16(dst + (uint32_t)i*16u, src + (size_t)i*16);
            CPA_COMMIT();
            CPA_WAIT1();
        } else {
            CPA_WAIT0();
        }
        __syncthreads();

        const __half* ysh = (const __half*)(smc + ((r & 1) ? YTILE_B : 0));

        u64 acc[10];
        #pragma unroll
        for (int p = 0; p < 10; p++) acc[p] = 0ull;
        #pragma unroll
        for (int k = 0; k < 3; k++) {
            const u64* Ab = (const u64*)(Ash + (size_t)((k*8 + g)*VNODES)*20);
            #pragma unroll
            for (int v = 0; v < VNODES; v++) {
                float yv = fmaf(__half2float(ysh[v*DK + k*DM + c]), sc[k], of[k]);
                u64 yp = pack2(yv, yv);
                const u64* ar = Ab + v*10;
                #pragma unroll
                for (int p = 0; p < 10; p++) ffma2(acc[p], yp, ar[p]);
            }
        }

        float z[20];
        #pragma unroll
        for (int p = 0; p < 10; p++) unpack2(acc[p], z[2*p], z[2*p+1]);

        const float* xb = X + nt * (size_t)(VNODES*DM) + c;
        float* ob = out + nt * (size_t)(VNODES*DM) + c;
        #pragma unroll
        for (int w = 0; w < VNODES; w++) {
            float zv = z[w] + xb[(size_t)w * DM];
            s_tot += zv; q_tot += zv*zv;
            ob[(size_t)w * DM] = zv;
        }
        __syncthreads();
    }
    atomicAdd(&g_stats1[c], s_tot);
    atomicAdd(&g_stats1[DM + c], q_tot);
}

__global__ void k_fin_bn1(const float* __restrict__ gamma, const float* __restrict__ beta) {
    int d = threadIdx.x;
    float inv = 1.0f / (float)MROWS;
    float mean = g_stats1[d] * inv;
    float var  = g_stats1[DM + d] * inv - mean*mean;
    float sc = gamma[d] * rsqrtf(var + 1e-5f);
    g_sb1[d]      = sc;
    g_sb1[DM + d] = beta[d] - mean*sc;
}

// ---------------------------------------------------------------------------
__global__ void k_relu(float* __restrict__ out) {
    size_t total4 = (size_t)MROWS * DM / 4;
    float4* o4 = (float4*)out;
    for (size_t i = (size_t)blockIdx.x * blockDim.x + threadIdx.x; i < total4;
         i += (size_t)gridDim.x * blockDim.x) {
        int c = (int)(i & 63) * 4;
        float4 v = o4[i];
        float4 sc = *(const float4*)&g_sb1[c];
        float4 of = *(const float4*)&g_sb1[DM + c];
        v.x = fmaxf(fmaf(v.x, sc.x, of.x), 0.f);
        v.y = fmaxf(fmaf(v.y, sc.y, of.y), 0.f);
        v.z = fmaxf(fmaf(v.z, sc.z, of.z), 0.f);
        v.w = fmaxf(fmaf(v.w, sc.w, of.w), 0.f);
        o4[i] = v;
    }
}

extern "C" void kernel_launch(void* const* d_in, const int* in_sizes, int n_in,
                              void* d_out, int out_size) {
    const float* x    = (const float*)d_in[0];
    const float* para = (const float*)d_in[1];
    const float* W    = (const float*)d_in[2];
    // d_in[3] linear_bias: cancels under training-mode BN (mean subtraction)
    const float* bng  = (const float*)d_in[4];
    const float* bnb  = (const float*)d_in[5];
    const float* bn1g = (const float*)d_in[6];
    const float* bn1b = (const float*)d_in[7];
    float* out = (float*)d_out;

    cudaFuncSetAttribute(k_contract, cudaFuncAttributeMaxDynamicSharedMemorySize,
                         SMEM_CONTRACT);
    cudaFuncSetAttribute(k_gemm_mma, cudaFuncAttributeMaxDynamicSharedMemorySize,
                         SMEM_GEMM);

    k_prep<<<1, 512>>>(para);
    k_split_w<<<96, 256>>>(W);
    k_gemm_mma<<<MTILES, GEMM_THREADS, SMEM_GEMM>>>(x);
    k_fin_bn<<<1, DK>>>(bng, bnb);
    k_contract<<<NT/4, 256, SMEM_CONTRACT>>>(x, out);
    k_fin_bn1<<<1, DM>>>(bn1g, bn1b);
    k_relu<<<2048, 256>>>(out);
}

// round 13
// speedup vs baseline: 1.7078x; 1.3134x over previous
#include <cuda_runtime.h>
#include <cuda_bf16.h>
#include <cuda_fp16.h>
#include <cstdint>

#define NBATCH 32
#define TLEN 256
#define VNODES 19
#define DM 256
#define DK 768
#define NT (NBATCH*TLEN)        // 8192
#define MROWS (NT*VNODES)       // 155648
#define MTILES (MROWS/128)      // 1216

typedef unsigned long long u64;

// scratch (device globals: allocation-free)
__device__ __half g_y[(size_t)MROWS * DK];              // GEMM output, fp16, ~239MB
__device__ __half g_bh[DK*256];                         // W^T fp16, swizzled n-major
__device__ float g_An[3*8*VNODES*20];                   // normalized adjacency (padded)
__device__ float g_stats[2*DK];
__device__ float g_sb[2*DK];
__device__ float g_stats1[2*DM];
__device__ float g_sb1[2*DM];

__device__ __forceinline__ u64 pack2(float x, float y){
    u64 r; asm("mov.b64 %0, {%1,%2};" : "=l"(r) : "f"(x), "f"(y)); return r;
}
__device__ __forceinline__ void unpack2(u64 v, float &x, float &y){
    asm("mov.b64 {%0,%1}, %2;" : "=f"(x), "=f"(y) : "l"(v));
}
__device__ __forceinline__ void ffma2(u64 &d, u64 a, u64 b){
    asm("fma.rn.f32x2 %0, %1, %2, %0;" : "+l"(d) : "l"(a), "l"(b));
}
__device__ __forceinline__ uint32_t smem_u32(const void* p){
    uint32_t a;
    asm("{ .reg .u64 t; cvta.to.shared.u64 t, %1; cvt.u32.u64 %0, t; }" : "=r"(a) : "l"(p));
    return a;
}
__device__ __forceinline__ void cpa16(uint32_t d, const void* s){
    asm volatile("cp.async.cg.shared.global [%0], [%1], 16;" :: "r"(d), "l"(s));
}
#define CPA_COMMIT() asm volatile("cp.async.commit_group;" ::: "memory")
#define CPA_WAIT0()  asm volatile("cp.async.wait_group 0;" ::: "memory")
#define CPA_WAIT1()  asm volatile("cp.async.wait_group 1;" ::: "memory")

#define LDSM4(r0,r1,r2,r3,addr) \
    asm volatile("ldmatrix.sync.aligned.m8n8.x4.shared.b16 {%0,%1,%2,%3}, [%4];" \
                 : "=r"(r0),"=r"(r1),"=r"(r2),"=r"(r3) : "r"(addr))

#define MMAF16(c,a,b0,b1) \
    asm volatile("mma.sync.aligned.m16n8k16.row.col.f32.f16.f16.f32 " \
                 "{%0,%1,%2,%3},{%4,%5,%6,%7},{%8,%9},{%0,%1,%2,%3};" \
                 : "+f"((c)[0]),"+f"((c)[1]),"+f"((c)[2]),"+f"((c)[3]) \
                 : "r"((a)[0]),"r"((a)[1]),"r"((a)[2]),"r"((a)[3]),"r"(b0),"r"(b1))

// ---------------------------------------------------------------------------
__global__ void k_prep(const float* __restrict__ para) {
    int tid = threadIdx.x;
    for (int i = tid; i < 2*DK; i += blockDim.x) g_stats[i] = 0.f;
    for (int i = tid; i < 2*DM; i += blockDim.x) g_stats1[i] = 0.f;
    if (tid < 3*8*VNODES) {
        const float* src = para + tid*VNODES;
        float ss = 0.f;
        #pragma unroll
        for (int w = 0; w < VNODES; w++) ss += src[w]*src[w];
        float inv = 1.0f / (sqrtf(ss) + 1e-4f);
        float* dst = g_An + tid*20;
        #pragma unroll
        for (int w = 0; w < VNODES; w++) dst[w] = src[w]*inv;
        dst[VNODES] = 0.f;
    }
}

// ---------------------------------------------------------------------------
// Convert W to fp16, transposed n-major [col][k], pre-swizzled.
// ---------------------------------------------------------------------------
__global__ void k_conv_w(const float* __restrict__ W) {
    int idx = blockIdx.x * blockDim.x + threadIdx.x;    // 768*32 = 24576
    if (idx >= DK*32) return;
    int c   = idx & 31;
    int col = idx >> 5;
    int k0 = c*8;
    uint32_t h[4];
    #pragma unroll
    for (int j = 0; j < 4; j++) {
        __half a = __float2half_rn(W[(size_t)(k0 + 2*j    )*DK + col]);
        __half b = __float2half_rn(W[(size_t)(k0 + 2*j + 1)*DK + col]);
        h[j] = (uint32_t)__half_as_ushort(a) | ((uint32_t)__half_as_ushort(b) << 16);
    }
    size_t dst = (size_t)col*512 + (size_t)((c ^ (col & 7)) << 4);
    *(uint4*)((char*)g_bh + dst) = make_uint4(h[0], h[1], h[2], h[3]);
}

// ---------------------------------------------------------------------------
// Single-pass fp16 tensor-core GEMM: y = X @ W, fp32 accumulate.
// A converted fp32->fp16 + swizzled inline in the prologue.
// 1216 CTAs x 128 rows; 512 threads = 4x4 warps, warp tile 32x16.
// 12 N-tiles of 64, cp.async double-buffered full B tiles (32KB each).
// Per k-chunk per warp: 3 ldmatrix.x4 + 4 MMA.
// smem: A 64KB | Btile[2] x 32KB = 128KB
// ---------------------------------------------------------------------------
#define GEMM_THREADS 512
#define OFF_B   65536u
#define B_TILE  32768u
#define SMEM_GEMM (65536 + 2*32768)   // 131072 B

__global__ void __launch_bounds__(GEMM_THREADS) k_gemm_mma(const float* __restrict__ X) {
    extern __shared__ char sm[];
    const int tid = threadIdx.x, lane = tid & 31, wid = tid >> 5;   // 0..15
    const int wm = wid & 3, wn = wid >> 2;     // 4 row-warps x 4 col-warps
    const size_t bm = blockIdx.x;

    const uint32_t sA = smem_u32(sm);

    // prologue: B tile 0 via cp.async (in flight), A converted inline
    #pragma unroll
    for (int u = 0; u < 4; u++) {
        int i = tid + u*512;                    // 0..2047
        cpa16(sA + OFF_B + (uint32_t)i*16u, (const char*)g_bh + (size_t)i*16);
    }
    CPA_COMMIT();
    {
        const float4* Xb = (const float4*)(X + bm*32768);
        #pragma unroll
        for (int u = 0; u < 16; u++) {
            int i = tid + u*512;
            int rr = i >> 6, c4 = i & 63;
            float4 v = Xb[i];
            union { __half h[4]; u64 u2; } hp;
            hp.h[0] = __float2half_rn(v.x);
            hp.h[1] = __float2half_rn(v.y);
            hp.h[2] = __float2half_rn(v.z);
            hp.h[3] = __float2half_rn(v.w);
            uint32_t base = (uint32_t)rr*512u
                          + ((((uint32_t)(c4 >> 1)) ^ (uint32_t)(rr & 7)) << 4)
                          + (uint32_t)((c4 & 1) * 8);
            *(u64*)(sm + base) = hp.u2;
        }
    }
    CPA_WAIT0();
    __syncthreads();

    const int rA    = wm*32 + (lane & 15);
    const int koffA = lane >> 4;
    const int rB    = wn*16 + (lane & 7) + ((lane >> 4) << 3);
    const int koffB = (lane >> 3) & 1;
    const int r0    = wm*32 + (lane >> 2);
    const uint32_t axor = (uint32_t)(rA & 7), bxor = (uint32_t)(rB & 7);
    const uint32_t aB = sA + (uint32_t)rA * 512;

    for (int nt = 0; nt < 12; nt++) {
        const int buf = nt & 1;
        // prefetch next B tile into the other buffer
        if (nt + 1 < 12) {
            uint32_t dst = sA + OFF_B + (uint32_t)(buf ^ 1) * B_TILE;
            const char* src = (const char*)g_bh + (size_t)(nt + 1) * B_TILE;
            #pragma unroll
            for (int u = 0; u < 4; u++) {
                int i = tid + u*512;
                cpa16(dst + (uint32_t)i*16u, src + (size_t)i*16);
            }
            CPA_COMMIT();
        }

        float acc[2][2][4];
        #pragma unroll
        for (int mi = 0; mi < 2; mi++)
            #pragma unroll
            for (int ni = 0; ni < 2; ni++)
                #pragma unroll
                for (int j = 0; j < 4; j++) acc[mi][ni][j] = 0.f;

        const uint32_t bB = sA + OFF_B + (uint32_t)buf * B_TILE + (uint32_t)rB * 512;

        #pragma unroll
        for (int kc = 0; kc < 16; kc++) {
            uint32_t ach = (((uint32_t)(kc*2 + koffA)) ^ axor) << 4;
            uint32_t bch = (((uint32_t)(kc*2 + koffB)) ^ bxor) << 4;
            uint32_t a0[4], a1[4], b[4];
            LDSM4(a0[0], a0[1], a0[2], a0[3], aB + ach);
            LDSM4(a1[0], a1[1], a1[2], a1[3], aB + 8192 + ach);
            LDSM4(b[0], b[1], b[2], b[3], bB + bch);
            MMAF16(acc[0][0], a0, b[0], b[1]);
            MMAF16(acc[0][1], a0, b[2], b[3]);
            MMAF16(acc[1][0], a1, b[0], b[1]);
            MMAF16(acc[1][1], a1, b[2], b[3]);
        }

        // epilogue: write g_y (fp16) + BN stats (fp32, exact)
        #pragma unroll
        for (int mi = 0; mi < 2; mi++) {
            #pragma unroll
            for (int ni = 0; ni < 2; ni++) {
                int cb = wn*16 + ni*8 + ((lane & 3) << 1);
                __half* p = g_y + (bm*128 + r0 + mi*16)*DK + nt*64 + cb;
                *(__half2*)p = __floats2half2_rn(acc[mi][ni][0], acc[mi][ni][1]);
                *(__half2*)(p + (size_t)8*DK) = __floats2half2_rn(acc[mi][ni][2], acc[mi][ni][3]);
            }
        }
        #pragma unroll
        for (int ni = 0; ni < 2; ni++) {
            float s0 = acc[0][ni][0] + acc[0][ni][2] + acc[1][ni][0] + acc[1][ni][2];
            float s1 = acc[0][ni][1] + acc[0][ni][3] + acc[1][ni][1] + acc[1][ni][3];
            float q0 = acc[0][ni][0]*acc[0][ni][0] + acc[0][ni][2]*acc[0][ni][2]
                     + acc[1][ni][0]*acc[1][ni][0] + acc[1][ni][2]*acc[1][ni][2];
            float q1 = acc[0][ni][1]*acc[0][ni][1] + acc[0][ni][3]*acc[0][ni][3]
                     + acc[1][ni][1]*acc[1][ni][1] + acc[1][ni][3]*acc[1][ni][3];
            #pragma unroll
            for (int off = 4; off < 32; off <<= 1) {
                s0 += __shfl_xor_sync(0xFFFFFFFFu, s0, off);
                s1 += __shfl_xor_sync(0xFFFFFFFFu, s1, off);
                q0 += __shfl_xor_sync(0xFFFFFFFFu, q0, off);
                q1 += __shfl_xor_sync(0xFFFFFFFFu, q1, off);
            }
            if (lane < 4) {
                int col = nt*64 + wn*16 + ni*8 + lane*2;
                atomicAdd(&g_stats[col],         s0);
                atomicAdd(&g_stats[col + 1],     s1);
                atomicAdd(&g_stats[DK + col],    q0);
                atomicAdd(&g_stats[DK + col+1],  q1);
            }
        }

        if (nt + 1 < 12) CPA_WAIT0();
        __syncthreads();
    }
}

// ---------------------------------------------------------------------------
__global__ void k_fin_bn(const float* __restrict__ gamma, const float* __restrict__ beta) {
    int d = threadIdx.x;
    float inv = 1.0f / (float)MROWS;
    float mean = g_stats[d] * inv;
    float var  = g_stats[DK + d] * inv - mean*mean;
    float sc = gamma[d] * rsqrtf(var + 1e-5f);
    g_sb[d]      = sc;
    g_sb[DK + d] = beta[d] - mean*sc;
}

// ---------------------------------------------------------------------------
// Per-(n,t): z[c,w] = sum_{k,v} yhat[v, k*256+c] * An[k, c%8, v, w] + x[n,t,w,c]
// 4 tiles per block, cp.async DOUBLE-BUFFERED fp16 y tiles.
// smem: ybuf[2] x 29184B + A 36480B = 94848 B -> 2 CTAs/SM
// ---------------------------------------------------------------------------
#define YTILE_E (VNODES*DK)          // 14592 elements
#define YTILE_B (YTILE_E*2)          // 29184 bytes (fp16)
#define SMEM_CONTRACT (2*YTILE_B + 3*8*VNODES*20*4)   // 94848 B

__global__ void __launch_bounds__(256, 2) k_contract(const float* __restrict__ X,
                                                     float* __restrict__ out) {
    extern __shared__ char smc[];
    float* Ash = (float*)(smc + 2*YTILE_B);
    const int tid = threadIdx.x;
    const size_t nt0 = (size_t)blockIdx.x * 4;
    const uint32_t sb = smem_u32(smc);

    for (int i = tid; i < 3*8*VNODES*20; i += 256) Ash[i] = g_An[i];
    {
        const char* src = (const char*)(g_y + nt0 * YTILE_E);
        for (int i = tid; i < YTILE_B/16; i += 256)
            cpa16(sb + (uint32_t)i*16u, src + (size_t)i*16);
        CPA_COMMIT();
    }

    const int c = tid, g = c & 7;
    float sc[3], of[3];
    #pragma unroll
    for (int k = 0; k < 3; k++) {
        sc[k] = g_sb[k*DM + c];
        of[k] = g_sb[DK + k*DM + c];
    }

    float s_tot = 0.f, q_tot = 0.f;

    for (int r = 0; r < 4; r++) {
        const size_t nt = nt0 + r;
        if (r < 3) {
            const char* src = (const char*)(g_y + (nt + 1) * YTILE_E);
            uint32_t dst = sb + (((r + 1) & 1) ? (uint32_t)YTILE_B : 0u);
            for (int i = tid; i < YTILE_B/16; i += 256)
                cpa16(dst + (uint32_t)i*16u, src + (size_t)i*16);
            CPA_COMMIT();
            CPA_WAIT1();
        } else {
            CPA_WAIT0();
        }
        __syncthreads();

        const __half* ysh = (const __half*)(smc + ((r & 1) ? YTILE_B : 0));

        u64 acc[10];
        #pragma unroll
        for (int p = 0; p < 10; p++) acc[p] = 0ull;
        #pragma unroll
        for (int k = 0; k < 3; k++) {
            const u64* Ab = (const u64*)(Ash + (size_t)((k*8 + g)*VNODES)*20);
            #pragma unroll
            for (int v = 0; v < VNODES; v++) {
                float yv = fmaf(__half2float(ysh[v*DK + k*DM + c]), sc[k], of[k]);
                u64 yp = pack2(yv, yv);
                const u64* ar = Ab + v*10;
                #pragma unroll
                for (int p = 0; p < 10; p++) ffma2(acc[p], yp, ar[p]);
            }
        }

        float z[20];
        #pragma unroll
        for (int p = 0; p < 10; p++) unpack2(acc[p], z[2*p], z[2*p+1]);

        const float* xb = X + nt * (size_t)(VNODES*DM) + c;
        float* ob = out + nt * (size_t)(VNODES*DM) + c;
        #pragma unroll
        for (int w = 0; w < VNODES; w++) {
            float zv = z[w] + xb[(size_t)w * DM];
            s_tot += zv; q_tot += zv*zv;
            ob[(size_t)w * DM] = zv;
        }
        __syncthreads();
    }
    atomicAdd(&g_stats1[c], s_tot);
    atomicAdd(&g_stats1[DM + c], q_tot);
}

__global__ void k_fin_bn1(const float* __restrict__ gamma, const float* __restrict__ beta) {
    int d = threadIdx.x;
    float inv = 1.0f / (float)MROWS;
    float mean = g_stats1[d] * inv;
    float var  = g_stats1[DM + d] * inv - mean*mean;
    float sc = gamma[d] * rsqrtf(var + 1e-5f);
    g_sb1[d]      = sc;
    g_sb1[DM + d] = beta[d] - mean*sc;
}

// ---------------------------------------------------------------------------
__global__ void k_relu(float* __restrict__ out) {
    size_t total4 = (size_t)MROWS * DM / 4;
    float4* o4 = (float4*)out;
    for (size_t i = (size_t)blockIdx.x * blockDim.x + threadIdx.x; i < total4;
         i += (size_t)gridDim.x * blockDim.x) {
        int c = (int)(i & 63) * 4;
        float4 v = o4[i];
        float4 sc = *(const float4*)&g_sb1[c];
        float4 of = *(const float4*)&g_sb1[DM + c];
        v.x = fmaxf(fmaf(v.x, sc.x, of.x), 0.f);
        v.y = fmaxf(fmaf(v.y, sc.y, of.y), 0.f);
        v.z = fmaxf(fmaf(v.z, sc.z, of.z), 0.f);
        v.w = fmaxf(fmaf(v.w, sc.w, of.w), 0.f);
        o4[i] = v;
    }
}

extern "C" void kernel_launch(void* const* d_in, const int* in_sizes, int n_in,
                              void* d_out, int out_size) {
    const float* x    = (const float*)d_in[0];
    const float* para = (const float*)d_in[1];
    const float* W    = (const float*)d_in[2];
    // d_in[3] linear_bias: cancels under training-mode BN (mean subtraction)
    const float* bng  = (const float*)d_in[4];
    const float* bnb  = (const float*)d_in[5];
    const float* bn1g = (const float*)d_in[6];
    const float* bn1b = (const float*)d_in[7];
    float* out = (float*)d_out;

    cudaFuncSetAttribute(k_contract, cudaFuncAttributeMaxDynamicSharedMemorySize,
                         SMEM_CONTRACT);
    cudaFuncSetAttribute(k_gemm_mma, cudaFuncAttributeMaxDynamicSharedMemorySize,
                         SMEM_GEMM);

    k_prep<<<1, 512>>>(para);
    k_conv_w<<<96, 256>>>(W);
    k_gemm_mma<<<MTILES, GEMM_THREADS, SMEM_GEMM>>>(x);
    k_fin_bn<<<1, DK>>>(bng, bnb);
    k_contract<<<NT/4, 256, SMEM_CONTRACT>>>(x, out);
    k_fin_bn1<<<1, DM>>>(bn1g, bn1b);
    k_relu<<<2048, 256>>>(out);
}

// round 14
// speedup vs baseline: 1.8229x; 1.0674x over previous
#include <cuda_runtime.h>
#include <cuda_bf16.h>
#include <cuda_fp16.h>
#include <cstdint>

#define NBATCH 32
#define TLEN 256
#define VNODES 19
#define DM 256
#define DK 768
#define NT (NBATCH*TLEN)        // 8192
#define MROWS (NT*VNODES)       // 155648
#define MTILES (MROWS/128)      // 1216

typedef unsigned long long u64;

// scratch (device globals: allocation-free)
__device__ __half g_y[(size_t)MROWS * DK];              // GEMM output, fp16, ~239MB
__device__ __half g_bh[DK*256];                         // W^T fp16, swizzled n-major
__device__ float g_An[3*8*VNODES*20];                   // normalized adjacency (padded)
__device__ float g_stats[2*DK];
__device__ float g_sb[2*DK];
__device__ float g_stats1[2*DM];
__device__ float g_sb1[2*DM];

__device__ __forceinline__ u64 pack2(float x, float y){
    u64 r; asm("mov.b64 %0, {%1,%2};" : "=l"(r) : "f"(x), "f"(y)); return r;
}
__device__ __forceinline__ void unpack2(u64 v, float &x, float &y){
    asm("mov.b64 {%0,%1}, %2;" : "=f"(x), "=f"(y) : "l"(v));
}
__device__ __forceinline__ void ffma2(u64 &d, u64 a, u64 b){
    asm("fma.rn.f32x2 %0, %1, %2, %0;" : "+l"(d) : "l"(a), "l"(b));
}
__device__ __forceinline__ uint32_t smem_u32(const void* p){
    uint32_t a;
    asm("{ .reg .u64 t; cvta.to.shared.u64 t, %1; cvt.u32.u64 %0, t; }" : "=r"(a) : "l"(p));
    return a;
}
__device__ __forceinline__ void cpa16(uint32_t d, const void* s){
    asm volatile("cp.async.cg.shared.global [%0], [%1], 16;" :: "r"(d), "l"(s));
}
#define CPA_COMMIT() asm volatile("cp.async.commit_group;" ::: "memory")
#define CPA_WAIT0()  asm volatile("cp.async.wait_group 0;" ::: "memory")
#define CPA_WAIT1()  asm volatile("cp.async.wait_group 1;" ::: "memory")

#define LDSM4(r0,r1,r2,r3,addr) \
    asm volatile("ldmatrix.sync.aligned.m8n8.x4.shared.b16 {%0,%1,%2,%3}, [%4];" \
                 : "=r"(r0),"=r"(r1),"=r"(r2),"=r"(r3) : "r"(addr))

#define MMAF16(c,a,b0,b1) \
    asm volatile("mma.sync.aligned.m16n8k16.row.col.f32.f16.f16.f32 " \
                 "{%0,%1,%2,%3},{%4,%5,%6,%7},{%8,%9},{%0,%1,%2,%3};" \
                 : "+f"((c)[0]),"+f"((c)[1]),"+f"((c)[2]),"+f"((c)[3]) \
                 : "r"((a)[0]),"r"((a)[1]),"r"((a)[2]),"r"((a)[3]),"r"(b0),"r"(b1))

// ---------------------------------------------------------------------------
__global__ void k_prep(const float* __restrict__ para) {
    int tid = threadIdx.x;
    for (int i = tid; i < 2*DK; i += blockDim.x) g_stats[i] = 0.f;
    for (int i = tid; i < 2*DM; i += blockDim.x) g_stats1[i] = 0.f;
    if (tid < 3*8*VNODES) {
        const float* src = para + tid*VNODES;
        float ss = 0.f;
        #pragma unroll
        for (int w = 0; w < VNODES; w++) ss += src[w]*src[w];
        float inv = 1.0f / (sqrtf(ss) + 1e-4f);
        float* dst = g_An + tid*20;
        #pragma unroll
        for (int w = 0; w < VNODES; w++) dst[w] = src[w]*inv;
        dst[VNODES] = 0.f;
    }
}

// ---------------------------------------------------------------------------
// Convert W to fp16, transposed n-major [col][k], pre-swizzled.
// ---------------------------------------------------------------------------
__global__ void k_conv_w(const float* __restrict__ W) {
    int idx = blockIdx.x * blockDim.x + threadIdx.x;    // 768*32 = 24576
    if (idx >= DK*32) return;
    int c   = idx & 31;
    int col = idx >> 5;
    int k0 = c*8;
    uint32_t h[4];
    #pragma unroll
    for (int j = 0; j < 4; j++) {
        __half a = __float2half_rn(W[(size_t)(k0 + 2*j    )*DK + col]);
        __half b = __float2half_rn(W[(size_t)(k0 + 2*j + 1)*DK + col]);
        h[j] = (uint32_t)__half_as_ushort(a) | ((uint32_t)__half_as_ushort(b) << 16);
    }
    size_t dst = (size_t)col*512 + (size_t)((c ^ (col & 7)) << 4);
    *(uint4*)((char*)g_bh + dst) = make_uint4(h[0], h[1], h[2], h[3]);
}

// ---------------------------------------------------------------------------
// Single-pass fp16 tensor-core GEMM: y = X @ W, fp32 accumulate.
// A converted fp32->fp16 + swizzled inline in the prologue.
// 1216 CTAs x 128 rows; 512 threads = 4x4 warps, warp tile 32x32.
// 6 N-tiles of 128, cp.async double-buffered B tiles (64KB each).
// Per k-chunk per warp: 4 ldmatrix.x4 + 8 MMA (balanced LDSM/MMA floors).
// smem: A 64KB | Btile[2] x 64KB = 192KB
// ---------------------------------------------------------------------------
#define GEMM_THREADS 512
#define OFF_B   65536u
#define B_TILE  65536u
#define SMEM_GEMM (65536 + 2*65536)   // 196608 B

__global__ void __launch_bounds__(GEMM_THREADS) k_gemm_mma(const float* __restrict__ X) {
    extern __shared__ char sm[];
    const int tid = threadIdx.x, lane = tid & 31, wid = tid >> 5;   // 0..15
    const int wm = wid & 3, wn = wid >> 2;     // 4 row-warps x 4 col-warps
    const size_t bm = blockIdx.x;

    const uint32_t sA = smem_u32(sm);

    // prologue: B tile 0 via cp.async (in flight), A converted inline
    #pragma unroll
    for (int u = 0; u < 8; u++) {
        int i = tid + u*512;                    // 0..4095
        cpa16(sA + OFF_B + (uint32_t)i*16u, (const char*)g_bh + (size_t)i*16);
    }
    CPA_COMMIT();
    {
        const float4* Xb = (const float4*)(X + bm*32768);
        #pragma unroll
        for (int u = 0; u < 16; u++) {
            int i = tid + u*512;
            int rr = i >> 6, c4 = i & 63;
            float4 v = Xb[i];
            union { __half h[4]; u64 u2; } hp;
            hp.h[0] = __float2half_rn(v.x);
            hp.h[1] = __float2half_rn(v.y);
            hp.h[2] = __float2half_rn(v.z);
            hp.h[3] = __float2half_rn(v.w);
            uint32_t base = (uint32_t)rr*512u
                          + ((((uint32_t)(c4 >> 1)) ^ (uint32_t)(rr & 7)) << 4)
                          + (uint32_t)((c4 & 1) * 8);
            *(u64*)(sm + base) = hp.u2;
        }
    }
    CPA_WAIT0();
    __syncthreads();

    const int rA    = wm*32 + (lane & 15);
    const int koffA = lane >> 4;
    const int rB    = wn*32 + (lane & 7) + ((lane >> 4) << 3);
    const int koffB = (lane >> 3) & 1;
    const int r0    = wm*32 + (lane >> 2);
    const uint32_t axor = (uint32_t)(rA & 7), bxor = (uint32_t)(rB & 7);
    const uint32_t aB = sA + (uint32_t)rA * 512;

    for (int nt = 0; nt < 6; nt++) {
        const int buf = nt & 1;
        // prefetch next B tile into the other buffer
        if (nt + 1 < 6) {
            uint32_t dst = sA + OFF_B + (uint32_t)(buf ^ 1) * B_TILE;
            const char* src = (const char*)g_bh + (size_t)(nt + 1) * B_TILE;
            #pragma unroll
            for (int u = 0; u < 8; u++) {
                int i = tid + u*512;
                cpa16(dst + (uint32_t)i*16u, src + (size_t)i*16);
            }
            CPA_COMMIT();
        }

        float acc[2][4][4];
        #pragma unroll
        for (int mi = 0; mi < 2; mi++)
            #pragma unroll
            for (int ni = 0; ni < 4; ni++)
                #pragma unroll
                for (int j = 0; j < 4; j++) acc[mi][ni][j] = 0.f;

        const uint32_t bB = sA + OFF_B + (uint32_t)buf * B_TILE + (uint32_t)rB * 512;

        #pragma unroll
        for (int kc = 0; kc < 16; kc++) {
            uint32_t ach = (((uint32_t)(kc*2 + koffA)) ^ axor) << 4;
            uint32_t bch = (((uint32_t)(kc*2 + koffB)) ^ bxor) << 4;
            uint32_t a0[4], a1[4], b0[4], b1[4];
            LDSM4(a0[0], a0[1], a0[2], a0[3], aB + ach);
            LDSM4(a1[0], a1[1], a1[2], a1[3], aB + 8192 + ach);
            LDSM4(b0[0], b0[1], b0[2], b0[3], bB + bch);
            LDSM4(b1[0], b1[1], b1[2], b1[3], bB + 8192 + bch);
            MMAF16(acc[0][0], a0, b0[0], b0[1]);
            MMAF16(acc[0][1], a0, b0[2], b0[3]);
            MMAF16(acc[0][2], a0, b1[0], b1[1]);
            MMAF16(acc[0][3], a0, b1[2], b1[3]);
            MMAF16(acc[1][0], a1, b0[0], b0[1]);
            MMAF16(acc[1][1], a1, b0[2], b0[3]);
            MMAF16(acc[1][2], a1, b1[0], b1[1]);
            MMAF16(acc[1][3], a1, b1[2], b1[3]);
        }

        // epilogue: write g_y (fp16) + BN stats (fp32, exact)
        #pragma unroll
        for (int mi = 0; mi < 2; mi++) {
            #pragma unroll
            for (int ni = 0; ni < 4; ni++) {
                int cb = wn*32 + ((ni >> 1) << 4) + ((ni & 1) << 3) + ((lane & 3) << 1);
                __half* p = g_y + (bm*128 + r0 + mi*16)*DK + nt*128 + cb;
                *(__half2*)p = __floats2half2_rn(acc[mi][ni][0], acc[mi][ni][1]);
                *(__half2*)(p + (size_t)8*DK) = __floats2half2_rn(acc[mi][ni][2], acc[mi][ni][3]);
            }
        }
        #pragma unroll
        for (int ni = 0; ni < 4; ni++) {
            float s0 = acc[0][ni][0] + acc[0][ni][2] + acc[1][ni][0] + acc[1][ni][2];
            float s1 = acc[0][ni][1] + acc[0][ni][3] + acc[1][ni][1] + acc[1][ni][3];
            float q0 = acc[0][ni][0]*acc[0][ni][0] + acc[0][ni][2]*acc[0][ni][2]
                     + acc[1][ni][0]*acc[1][ni][0] + acc[1][ni][2]*acc[1][ni][2];
            float q1 = acc[0][ni][1]*acc[0][ni][1] + acc[0][ni][3]*acc[0][ni][3]
                     + acc[1][ni][1]*acc[1][ni][1] + acc[1][ni][3]*acc[1][ni][3];
            #pragma unroll
            for (int off = 4; off < 32; off <<= 1) {
                s0 += __shfl_xor_sync(0xFFFFFFFFu, s0, off);
                s1 += __shfl_xor_sync(0xFFFFFFFFu, s1, off);
                q0 += __shfl_xor_sync(0xFFFFFFFFu, q0, off);
                q1 += __shfl_xor_sync(0xFFFFFFFFu, q1, off);
            }
            if (lane < 4) {
                int col = nt*128 + wn*32 + ((ni >> 1) << 4) + ((ni & 1) << 3) + lane*2;
                atomicAdd(&g_stats[col],         s0);
                atomicAdd(&g_stats[col + 1],     s1);
                atomicAdd(&g_stats[DK + col],    q0);
                atomicAdd(&g_stats[DK + col+1],  q1);
            }
        }

        if (nt + 1 < 6) CPA_WAIT0();
        __syncthreads();
    }
}

// ---------------------------------------------------------------------------
__global__ void k_fin_bn(const float* __restrict__ gamma, const float* __restrict__ beta) {
    int d = threadIdx.x;
    float inv = 1.0f / (float)MROWS;
    float mean = g_stats[d] * inv;
    float var  = g_stats[DK + d] * inv - mean*mean;
    float sc = gamma[d] * rsqrtf(var + 1e-5f);
    g_sb[d]      = sc;
    g_sb[DK + d] = beta[d] - mean*sc;
}

// ---------------------------------------------------------------------------
// Per-(n,t): z[c,w] = sum_{k,v} yhat[v, k*256+c] * An[k, c%8, v, w] + x[n,t,w,c]
// 4 tiles per block, cp.async DOUBLE-BUFFERED fp16 y tiles.
// smem: ybuf[2] x 29184B + A 36480B = 94848 B -> 2 CTAs/SM
// ---------------------------------------------------------------------------
#define YTILE_E (VNODES*DK)          // 14592 elements
#define YTILE_B (YTILE_E*2)          // 29184 bytes (fp16)
#define SMEM_CONTRACT (2*YTILE_B + 3*8*VNODES*20*4)   // 94848 B

__global__ void __launch_bounds__(256, 2) k_contract(const float* __restrict__ X,
                                                     float* __restrict__ out) {
    extern __shared__ char smc[];
    float* Ash = (float*)(smc + 2*YTILE_B);
    const int tid = threadIdx.x;
    const size_t nt0 = (size_t)blockIdx.x * 4;
    const uint32_t sb = smem_u32(smc);

    for (int i = tid; i < 3*8*VNODES*20; i += 256) Ash[i] = g_An[i];
    {
        const char* src = (const char*)(g_y + nt0 * YTILE_E);
        for (int i = tid; i < YTILE_B/16; i += 256)
            cpa16(sb + (uint32_t)i*16u, src + (size_t)i*16);
        CPA_COMMIT();
    }

    const int c = tid, g = c & 7;
    float sc[3], of[3];
    #pragma unroll
    for (int k = 0; k < 3; k++) {
        sc[k] = g_sb[k*DM + c];
        of[k] = g_sb[DK + k*DM + c];
    }

    float s_tot = 0.f, q_tot = 0.f;

    for (int r = 0; r < 4; r++) {
        const size_t nt = nt0 + r;
        if (r < 3) {
            const char* src = (const char*)(g_y + (nt + 1) * YTILE_E);
            uint32_t dst = sb + (((r + 1) & 1) ? (uint32_t)YTILE_B : 0u);
            for (int i = tid; i < YTILE_B/16; i += 256)
                cpa16(dst + (uint32_t)i*16u, src + (size_t)i*16);
            CPA_COMMIT();
            CPA_WAIT1();
        } else {
            CPA_WAIT0();
        }
        __syncthreads();

        const __half* ysh = (const __half*)(smc + ((r & 1) ? YTILE_B : 0));

        u64 acc[10];
        #pragma unroll
        for (int p = 0; p < 10; p++) acc[p] = 0ull;
        #pragma unroll
        for (int k = 0; k < 3; k++) {
            const u64* Ab = (const u64*)(Ash + (size_t)((k*8 + g)*VNODES)*20);
            #pragma unroll
            for (int v = 0; v < VNODES; v++) {
                float yv = fmaf(__half2float(ysh[v*DK + k*DM + c]), sc[k], of[k]);
                u64 yp = pack2(yv, yv);
                const u64* ar = Ab + v*10;
                #pragma unroll
                for (int p = 0; p < 10; p++) ffma2(acc[p], yp, ar[p]);
            }
        }

        float z[20];
        #pragma unroll
        for (int p = 0; p < 10; p++) unpack2(acc[p], z[2*p], z[2*p+1]);

        const float* xb = X + nt * (size_t)(VNODES*DM) + c;
        float* ob = out + nt * (size_t)(VNODES*DM) + c;
        #pragma unroll
        for (int w = 0; w < VNODES; w++) {
            float zv = z[w] + xb[(size_t)w * DM];
            s_tot += zv; q_tot += zv*zv;
            ob[(size_t)w * DM] = zv;
        }
        __syncthreads();
    }
    atomicAdd(&g_stats1[c], s_tot);
    atomicAdd(&g_stats1[DM + c], q_tot);
}

__global__ void k_fin_bn1(const float* __restrict__ gamma, const float* __restrict__ beta) {
    int d = threadIdx.x;
    float inv = 1.0f / (float)MROWS;
    float mean = g_stats1[d] * inv;
    float var  = g_stats1[DM + d] * inv - mean*mean;
    float sc = gamma[d] * rsqrtf(var + 1e-5f);
    g_sb1[d]      = sc;
    g_sb1[DM + d] = beta[d] - mean*sc;
}

// ---------------------------------------------------------------------------
__global__ void k_relu(float* __restrict__ out) {
    size_t total4 = (size_t)MROWS * DM / 4;
    float4* o4 = (float4*)out;
    for (size_t i = (size_t)blockIdx.x * blockDim.x + threadIdx.x; i < total4;
         i += (size_t)gridDim.x * blockDim.x) {
        int c = (int)(i & 63) * 4;
        float4 v = o4[i];
        float4 sc = *(const float4*)&g_sb1[c];
        float4 of = *(const float4*)&g_sb1[DM + c];
        v.x = fmaxf(fmaf(v.x, sc.x, of.x), 0.f);
        v.y = fmaxf(fmaf(v.y, sc.y, of.y), 0.f);
        v.z = fmaxf(fmaf(v.z, sc.z, of.z), 0.f);
        v.w = fmaxf(fmaf(v.w, sc.w, of.w), 0.f);
        o4[i] = v;
    }
}

extern "C" void kernel_launch(void* const* d_in, const int* in_sizes, int n_in,
                              void* d_out, int out_size) {
    const float* x    = (const float*)d_in[0];
    const float* para = (const float*)d_in[1];
    const float* W    = (const float*)d_in[2];
    // d_in[3] linear_bias: cancels under training-mode BN (mean subtraction)
    const float* bng  = (const float*)d_in[4];
    const float* bnb  = (const float*)d_in[5];
    const float* bn1g = (const float*)d_in[6];
    const float* bn1b = (const float*)d_in[7];
    float* out = (float*)d_out;

    cudaFuncSetAttribute(k_contract, cudaFuncAttributeMaxDynamicSharedMemorySize,
                         SMEM_CONTRACT);
    cudaFuncSetAttribute(k_gemm_mma, cudaFuncAttributeMaxDynamicSharedMemorySize,
                         SMEM_GEMM);

    k_prep<<<1, 512>>>(para);
    k_conv_w<<<96, 256>>>(W);
    k_gemm_mma<<<MTILES, GEMM_THREADS, SMEM_GEMM>>>(x);
    k_fin_bn<<<1, DK>>>(bng, bnb);
    k_contract<<<NT/4, 256, SMEM_CONTRACT>>>(x, out);
    k_fin_bn1<<<1, DM>>>(bn1g, bn1b);
    k_relu<<<2048, 256>>>(out);
}